// round 8
// baseline (speedup 1.0000x reference)
#include <cuda_runtime.h>
#include <cuda_bf16.h>
#include <math.h>

#define BB 2
#define NN 1024
#define TOK (BB*NN)
#define DIM 1024
#define DQK 128
#define NKEY 256
#define TOPK 32
#define DV 512
#define KCONV 5
#define OUT_MAIN (TOK*1024)

__device__ float g_invrms[TOK];
__device__ float g_x2[TOK*DIM];
__device__ float g_qpart[4*TOK*DQK];
__device__ float g_sc[TOK*1024];
__device__ float g_fs[2*TOK*TOPK];
__device__ int   g_fidx[2*TOK*TOPK];
// bf16 splits: q (after LN) and permuted keys
__device__ __nv_bfloat16 g_qh[TOK*DQK], g_qm[TOK*DQK], g_ql[TOK*DQK];
__device__ __nv_bfloat16 g_kh[1024*DQK], g_km[1024*DQK], g_kl[1024*DQK];

__device__ __forceinline__ float fsign(float a, float b){ return (b >= 0.f) ? fabsf(a) : -fabsf(a); }
__device__ __forceinline__ unsigned sortable_f(float f){
    unsigned u = __float_as_uint(f);
    return (u & 0x80000000u) ? ~u : (u | 0x80000000u);
}
__device__ __forceinline__ float unsortable_f(unsigned s){
    unsigned u = (s & 0x80000000u) ? (s ^ 0x80000000u) : ~s;
    return __uint_as_float(u);
}
__device__ __forceinline__ unsigned long long pack_key(float v, unsigned idx){
    return (((unsigned long long)sortable_f(v)) << 32) | (unsigned long long)(0xFFFFFFFFu - idx);
}

// ---------------- LAPACK slasv2 port ----------------
__device__ void slasv2_dev(float f, float g, float h,
                           float& ssmin, float& ssmax,
                           float& snr, float& csr, float& snl, float& csl)
{
    float ft=f, fa=fabsf(f), ht=h, ha=fabsf(h);
    int pmax = 1;
    bool swp = (ha > fa);
    if (swp){ pmax = 3; float t; t=ft; ft=ht; ht=t; t=fa; fa=ha; ha=t; }
    float gt=g, ga=fabsf(g);
    float clt=0.f, crt=0.f, slt=0.f, srt=0.f;
    if (ga == 0.f){
        ssmin = ha; ssmax = fa; clt=1.f; crt=1.f; slt=0.f; srt=0.f;
    } else {
        bool gasmal = true;
        if (ga > fa){
            pmax = 2;
            if ((fa/ga) < 5.9604645e-08f){
                gasmal = false;
                ssmax = ga;
                ssmin = (ha > 1.f) ? (fa/(ga/ha)) : ((fa/ga)*ha);
                clt = 1.f; slt = ht/gt; srt = 1.f; crt = ft/gt;
            }
        }
        if (gasmal){
            float d_ = fa - ha;
            float l  = (d_ == fa) ? 1.f : d_/fa;
            float m  = gt/ft;
            float t  = 2.f - l;
            float mm = m*m, tt = t*t;
            float s  = sqrtf(tt + mm);
            float r_ = (l == 0.f) ? fabsf(m) : sqrtf(l*l + mm);
            float a_ = 0.5f*(s + r_);
            ssmin = ha/a_;
            ssmax = fa*a_;
            if (mm == 0.f){
                t = (l == 0.f) ? (fsign(2.f, ft)*fsign(1.f, gt))
                               : (gt/fsign(d_, ft) + m/t);
            } else {
                t = (m/(s + t) + m/(r_ + l))*(1.f + a_);
            }
            float l2 = sqrtf(t*t + 4.f);
            crt = 2.f/l2;
            srt = t/l2;
            clt = (crt + srt*m)/a_;
            slt = (ht/ft)*srt/a_;
        }
    }
    if (swp){ csl = srt; snl = crt; csr = slt; snr = clt; }
    else    { csl = clt; snl = slt; csr = crt; snr = srt; }
    float ts = 0.f;
    if (pmax == 1) ts = fsign(1.f, csr)*fsign(1.f, csl)*fsign(1.f, f);
    if (pmax == 2) ts = fsign(1.f, snr)*fsign(1.f, csl)*fsign(1.f, g);
    if (pmax == 3) ts = fsign(1.f, snr)*fsign(1.f, snl)*fsign(1.f, h);
    ssmax = fsign(ssmax, ts);
    ssmin = fsign(ssmin, ts*fsign(1.f, f)*fsign(1.f, h));
}

__device__ void svd2x2(const float* core, int hh, float& u0, float& u1,
                       float& t0, float& t1, float& auxp)
{
    float a = core[hh*4+0], b = core[hh*4+1];
    float c = core[hh*4+2], d = core[hh*4+3];
    float q00=1.f,q01=0.f,q10=0.f,q11=1.f;
    float d1, e1, d2;
    if (c != 0.f){
        float nrm  = sqrtf(a*a + c*c);
        float beta = (a >= 0.f) ? -nrm : nrm;
        float tau  = (beta - a)/beta;
        float v    = c/(a - beta);
        float w    = b + v*d;
        e1 = b - tau*w;
        d2 = d - tau*v*w;
        d1 = beta;
        q00 = 1.f - tau; q01 = -tau*v; q10 = -tau*v; q11 = 1.f - tau*v*v;
    } else { d1 = a; e1 = b; d2 = d; }
    float ssmin, ssmax, snr, csr, snl, csl;
    slasv2_dev(d1, e1, d2, ssmin, ssmax, snr, csr, snl, csl);
    float vt0 = csr, vt1 = snr;
    float s1 = ssmax;
    if (s1 < 0.f){ s1 = -s1; vt0 = -vt0; vt1 = -vt1; }
    float s2 = fabsf(ssmin);
    u0 = q00*csl + q01*snl;
    u1 = q10*csl + q11*snl;
    t0 = vt0;
    t1 = vt1;
    float r = s2 - 0.15f;
    auxp = (r > 0.f) ? r*r : 0.f;
}

__global__ void rms_kernel(const float* __restrict__ tokens)
{
    int tok = blockIdx.x;
    const float4* p = (const float4*)(tokens + (size_t)tok*DIM);
    float4 v = p[threadIdx.x];
    float s = v.x*v.x + v.y*v.y + v.z*v.z + v.w*v.w;
    for (int o = 16; o; o >>= 1) s += __shfl_xor_sync(0xFFFFFFFFu, s, o);
    __shared__ float ws[8];
    if ((threadIdx.x & 31) == 0) ws[threadIdx.x >> 5] = s;
    __syncthreads();
    if (threadIdx.x == 0){
        float t = 0.f;
        #pragma unroll
        for (int i = 0; i < 8; i++) t += ws[i];
        g_invrms[tok] = rsqrtf(t*(1.f/1024.f) + 1.1920929e-07f);
    }
}

__global__ void conv_kernel(const float* __restrict__ tokens,
                            const float* __restrict__ rms_w,
                            const float* __restrict__ conv_w,
                            const float* __restrict__ conv_b)
{
    int gid = blockIdx.x*256 + threadIdx.x;
    int d   = gid & (DIM-1);
    int grp = gid >> 10;
    int ng  = grp & (NN/4 - 1);
    int bb  = grp >> 8;
    float rw = rms_w[d];
    float wv[KCONV];
    #pragma unroll
    for (int k = 0; k < KCONV; k++) wv[k] = conv_w[d*KCONV + k];
    float xv[8];
    #pragma unroll
    for (int j = 0; j < 8; j++){
        int nn = ng*4 - 4 + j;
        if (nn >= 0){
            int t2 = (bb << 10) + nn;
            xv[j] = tokens[(size_t)t2*DIM + d] * g_invrms[t2] * rw;
        } else xv[j] = 0.f;
    }
    float cb = conv_b[d];
    #pragma unroll
    for (int i = 0; i < 4; i++){
        float acc = cb;
        #pragma unroll
        for (int k = 0; k < KCONV; k++) acc += wv[k]*xv[i+k];
        g_x2[(size_t)((bb << 10) + ng*4 + i)*DIM + d] = acc;
    }
}

// GEMM1: qpart[z] = x2 @ wq^T, split-K=4
__global__ __launch_bounds__(256) void gemm_q(const float* __restrict__ A,
                                              const float* __restrict__ B,
                                              float* __restrict__ C)
{
    __shared__ float As[2][16][132];
    __shared__ float Bs[2][16][68];
    int tid = threadIdx.x, tx = tid & 15, ty = tid >> 4;
    int m0 = blockIdx.y*128, n0 = blockIdx.x*64, k0 = blockIdx.z*256;
    C += (size_t)blockIdx.z*(TOK*DQK);
    const float* Ab = A + (size_t)m0*DIM + k0;
    const float* Bb = B + (size_t)n0*DIM + k0;
    float acc[8][4];
    #pragma unroll
    for (int i = 0; i < 8; i++)
        #pragma unroll
        for (int j = 0; j < 4; j++) acc[i][j] = 0.f;
    float ra[8], rb[4];
    #pragma unroll
    for (int e = 0; e < 8; e++){ int f = tid + e*256; ra[e] = Ab[(size_t)(f >> 4)*DIM + (f & 15)]; }
    #pragma unroll
    for (int e = 0; e < 4; e++){ int f = tid + e*256; rb[e] = Bb[(size_t)(f >> 4)*DIM + (f & 15)]; }
    #pragma unroll
    for (int e = 0; e < 8; e++){ int f = tid + e*256; As[0][f & 15][f >> 4] = ra[e]; }
    #pragma unroll
    for (int e = 0; e < 4; e++){ int f = tid + e*256; Bs[0][f & 15][f >> 4] = rb[e]; }
    __syncthreads();
    int cur = 0;
    for (int kk = 0; kk < 256; kk += 16){
        bool nxt = (kk + 16) < 256;
        if (nxt){
            #pragma unroll
            for (int e = 0; e < 8; e++){ int f = tid + e*256; ra[e] = Ab[(size_t)(f >> 4)*DIM + kk + 16 + (f & 15)]; }
            #pragma unroll
            for (int e = 0; e < 4; e++){ int f = tid + e*256; rb[e] = Bb[(size_t)(f >> 4)*DIM + kk + 16 + (f & 15)]; }
        }
        #pragma unroll
        for (int k = 0; k < 16; k++){
            float4 a0 = *(const float4*)&As[cur][k][ty*8];
            float4 a1 = *(const float4*)&As[cur][k][ty*8+4];
            float4 b0 = *(const float4*)&Bs[cur][k][tx*4];
            float a[8] = {a0.x,a0.y,a0.z,a0.w,a1.x,a1.y,a1.z,a1.w};
            float b[4] = {b0.x,b0.y,b0.z,b0.w};
            #pragma unroll
            for (int i = 0; i < 8; i++)
                #pragma unroll
                for (int j = 0; j < 4; j++)
                    acc[i][j] += a[i]*b[j];
        }
        if (nxt){
            #pragma unroll
            for (int e = 0; e < 8; e++){ int f = tid + e*256; As[cur^1][f & 15][f >> 4] = ra[e]; }
            #pragma unroll
            for (int e = 0; e < 4; e++){ int f = tid + e*256; Bs[cur^1][f & 15][f >> 4] = rb[e]; }
            __syncthreads();
            cur ^= 1;
        }
    }
    #pragma unroll
    for (int i = 0; i < 8; i++){
        float4 v = {acc[i][0], acc[i][1], acc[i][2], acc[i][3]};
        *(float4*)(C + (size_t)(m0 + ty*8 + i)*DQK + n0 + tx*4) = v;
    }
}

// sum split-K partials + LayerNorm + emit bf16 3-way split of q
__global__ void ln_kernel(const float* __restrict__ qln_w)
{
    int tok = blockIdx.x, t = threadIdx.x;
    float v = 0.f;
    #pragma unroll
    for (int z = 0; z < 4; z++) v += g_qpart[(size_t)z*TOK*DQK + tok*DQK + t];
    float s = v;
    for (int o = 16; o; o >>= 1) s += __shfl_xor_sync(0xFFFFFFFFu, s, o);
    __shared__ float ws[4], ws2[4];
    int w = t >> 5, l = t & 31;
    if (l == 0) ws[w] = s;
    __syncthreads();
    float mu = (ws[0]+ws[1]+ws[2]+ws[3]) * (1.f/128.f);
    float dv = v - mu;
    float s2 = dv*dv;
    for (int o = 16; o; o >>= 1) s2 += __shfl_xor_sync(0xFFFFFFFFu, s2, o);
    if (l == 0) ws2[w] = s2;
    __syncthreads();
    float var = (ws2[0]+ws2[1]+ws2[2]+ws2[3]) * (1.f/128.f);
    float q = dv * rsqrtf(var + 1e-5f) * qln_w[t];
    __nv_bfloat16 h = __float2bfloat16(q);
    float fh = __bfloat162float(h);
    __nv_bfloat16 m = __float2bfloat16(q - fh);
    float fm = __bfloat162float(m);
    __nv_bfloat16 lo = __float2bfloat16(q - fh - fm);
    int idx = tok*DQK + t;
    g_qh[idx] = h; g_qm[idx] = m; g_ql[idx] = lo;
}

// permute keys and emit bf16 3-way split
__global__ void ksplit_kernel(const float* __restrict__ keys)
{
    int gid = blockIdx.x*256 + threadIdx.x;   // 1024*128
    int d = gid & 127, j = gid >> 7;
    int c = j >> 9, rem = j & 511, m = rem >> 1, r = rem & 1;
    float v = keys[(((c*2 + r)*NKEY + m)*DQK) + d];
    __nv_bfloat16 h = __float2bfloat16(v);
    float fh = __bfloat162float(h);
    __nv_bfloat16 mm = __float2bfloat16(v - fh);
    float fm = __bfloat162float(mm);
    __nv_bfloat16 lo = __float2bfloat16(v - fh - fm);
    g_kh[gid] = h; g_km[gid] = mm; g_kl[gid] = lo;
}

__device__ __forceinline__ void mma16816(float* d, const unsigned* a, const unsigned* b){
    asm volatile("mma.sync.aligned.m16n8k16.row.col.f32.bf16.bf16.f32 "
        "{%0,%1,%2,%3}, {%4,%5,%6,%7}, {%8,%9}, {%0,%1,%2,%3};"
        : "+f"(d[0]), "+f"(d[1]), "+f"(d[2]), "+f"(d[3])
        : "r"(a[0]), "r"(a[1]), "r"(a[2]), "r"(a[3]), "r"(b[0]), "r"(b[1]));
}

// GEMM2 via bf16 split-3 tensor MMA: sc[2048][1024] = q @ kp^T
// block: 256 thr = 8 warps (4m x 2n); warp tile m32 x n32; block tile M128 x N64
__global__ __launch_bounds__(256) void gemm_sc_mma(float* __restrict__ C)
{
    int tid = threadIdx.x;
    int w = tid >> 5, lane = tid & 31;
    int g = lane >> 2, tg = lane & 3;
    int wm = w >> 1, wn = w & 1;
    int m0 = blockIdx.y*128 + wm*32;
    int n0 = blockIdx.x*64 + wn*32;
    const __nv_bfloat16* Asp[3];
    Asp[0] = g_qh; Asp[1] = g_qm; Asp[2] = g_ql;
    const __nv_bfloat16* Bsp[3];
    Bsp[0] = g_kh; Bsp[1] = g_km; Bsp[2] = g_kl;
    float acc[2][4][4];
    #pragma unroll
    for (int i = 0; i < 2; i++)
        #pragma unroll
        for (int j = 0; j < 4; j++)
            #pragma unroll
            for (int e = 0; e < 4; e++) acc[i][j][e] = 0.f;
    #pragma unroll
    for (int k0 = 0; k0 < 128; k0 += 16){
        unsigned a[3][2][4], b[3][4][2];
        #pragma unroll
        for (int s = 0; s < 3; s++){
            const __nv_bfloat16* P = Asp[s];
            #pragma unroll
            for (int mt = 0; mt < 2; mt++){
                int r0 = m0 + mt*16 + g;
                int c  = k0 + tg*2;
                a[s][mt][0] = *(const unsigned*)(P + (size_t)r0*DQK + c);
                a[s][mt][1] = *(const unsigned*)(P + (size_t)(r0+8)*DQK + c);
                a[s][mt][2] = *(const unsigned*)(P + (size_t)r0*DQK + c + 8);
                a[s][mt][3] = *(const unsigned*)(P + (size_t)(r0+8)*DQK + c + 8);
            }
            const __nv_bfloat16* Q = Bsp[s];
            #pragma unroll
            for (int nt = 0; nt < 4; nt++){
                int n = n0 + nt*8 + g;
                int c = k0 + tg*2;
                b[s][nt][0] = *(const unsigned*)(Q + (size_t)n*DQK + c);
                b[s][nt][1] = *(const unsigned*)(Q + (size_t)n*DQK + c + 8);
            }
        }
        const int pa[8] = {0,0,1,1,0,2,1,2};
        const int pb[8] = {0,1,0,1,2,0,2,1};
        #pragma unroll
        for (int p = 0; p < 8; p++)
            #pragma unroll
            for (int mt = 0; mt < 2; mt++)
                #pragma unroll
                for (int nt = 0; nt < 4; nt++)
                    mma16816(acc[mt][nt], a[pa[p]][mt], b[pb[p]][nt]);
    }
    #pragma unroll
    for (int mt = 0; mt < 2; mt++){
        #pragma unroll
        for (int nt = 0; nt < 4; nt++){
            int row = m0 + mt*16 + g;
            int col = n0 + nt*8 + tg*2;
            float2 v0 = {acc[mt][nt][0], acc[mt][nt][1]};
            float2 v1 = {acc[mt][nt][2], acc[mt][nt][3]};
            *(float2*)(C + (size_t)row*1024 + col) = v0;
            *(float2*)(C + (size_t)(row+8)*1024 + col) = v1;
        }
    }
}

// ---------------- block-wide exact top-32 threshold via MSB radix descent ----------------
__device__ unsigned long long radix_select32(const unsigned long long* kv, int npt, int tid,
                                             unsigned* hist, unsigned* sh)
{
    unsigned long long prefix = 0;
    bool act[4] = {true, true, true, true};
    int need = 32;
    int lane = tid & 31, w = tid >> 5;
    for (int shift = 56; shift >= 0; shift -= 8){
        hist[tid] = 0;
        __syncthreads();
        #pragma unroll
        for (int e = 0; e < 4; e++)
            if (e < npt && act[e])
                atomicAdd(&hist[(unsigned)((kv[e] >> shift) & 255)], 1u);
        __syncthreads();
        unsigned h = hist[tid];
        unsigned inc = h;
        #pragma unroll
        for (int off = 1; off < 32; off <<= 1){
            unsigned v = __shfl_down_sync(0xFFFFFFFFu, inc, off);
            if (lane + off < 32) inc += v;
        }
        if (lane == 0) sh[8 + w] = inc;
        __syncthreads();
        unsigned upper = 0;
        #pragma unroll
        for (int ww = 1; ww < 8; ww++) if (ww > w) upper += sh[8 + ww];
        unsigned cge = inc + upper;
        unsigned cgt = cge - h;
        if (cgt < (unsigned)need && cge >= (unsigned)need){
            sh[0] = (unsigned)tid;
            sh[1] = (unsigned)need - cgt;
            sh[2] = (h == (unsigned)need - cgt) ? 1u : 0u;
        }
        __syncthreads();
        unsigned D = sh[0];
        need = (int)sh[1];
        unsigned done = sh[2];
        prefix |= ((unsigned long long)D) << shift;
        if (done) return prefix;
        #pragma unroll
        for (int e = 0; e < 4; e++)
            if (e < npt)
                act[e] = act[e] && (((kv[e] >> shift) & 255) == (unsigned long long)D);
        __syncthreads();
    }
    return prefix;
}

__global__ __launch_bounds__(256) void select_kernel(const float* __restrict__ core,
                                                     float* __restrict__ d_out, int out_size)
{
    __shared__ float rs[1024];
    __shared__ unsigned hist[256];
    __shared__ unsigned sh[16];
    __shared__ int ridx[32], cidx[32];
    __shared__ float gg0[32], gg1[32], fc0[32], fc1[32];
    __shared__ float suv[8];
    __shared__ int cnt;
    int tok = blockIdx.x, tid = threadIdx.x;
    if (tid == 0){
        float aux = 0.f;
        #pragma unroll
        for (int hh = 0; hh < 2; hh++){
            float u0,u1,t0,t1,ap;
            svd2x2(core, hh, u0, u1, t0, t1, ap);
            suv[hh*4+0]=u0; suv[hh*4+1]=u1; suv[hh*4+2]=t0; suv[hh*4+3]=t1;
            aux += ap;
        }
        if (tok == 0 && out_size > OUT_MAIN) d_out[OUT_MAIN] = aux*0.1f;
    }
    #pragma unroll
    for (int e = 0; e < 4; e++) rs[tid + e*256] = g_sc[(size_t)tok*1024 + tid + e*256];
    __syncthreads();

    for (int h = 0; h < 2; h++){
        float u0 = suv[h*4+0], u1 = suv[h*4+1];
        float t0 = suv[h*4+2], t1 = suv[h*4+3];
        float c00 = core[h*4+0], c01 = core[h*4+1], c10 = core[h*4+2], c11 = core[h*4+3];

        if (tid == 0) cnt = 0;
        unsigned long long kr = pack_key(rs[2*tid]*u0 + rs[2*tid+1]*u1, (unsigned)tid);
        unsigned long long T = radix_select32(&kr, 1, tid, hist, sh);
        if (kr >= T){ int s = atomicAdd(&cnt, 1); ridx[s] = tid; }
        __syncthreads();
        if (tid < 32){
            int mi = ridx[tid];
            float f0 = rs[2*mi], f1 = rs[2*mi+1];
            gg0[tid] = f0*c00 + f1*c10;
            gg1[tid] = f0*c01 + f1*c11;
        }

        if (tid == 0) cnt = 0;
        unsigned long long kc = pack_key(rs[512 + 2*tid]*t0 + rs[512 + 2*tid+1]*t1, (unsigned)tid);
        T = radix_select32(&kc, 1, tid, hist, sh);
        if (kc >= T){ int s = atomicAdd(&cnt, 1); cidx[s] = tid; }
        __syncthreads();
        if (tid < 32){
            int mi = cidx[tid];
            fc0[tid] = rs[512 + 2*mi];
            fc1[tid] = rs[512 + 2*mi+1];
        }
        __syncthreads();

        if (tid == 0) cnt = 0;
        unsigned long long kv[4];
        #pragma unroll
        for (int c = 0; c < 4; c++){
            int p = c*256 + tid;
            int i = p >> 5, j = p & 31;
            float val = gg0[i]*fc0[j] + gg1[i]*fc1[j];
            kv[c] = pack_key(val, (unsigned)p);
        }
        T = radix_select32(kv, 4, tid, hist, sh);
        #pragma unroll
        for (int c = 0; c < 4; c++){
            if (kv[c] >= T){
                int s = atomicAdd(&cnt, 1);
                int p = (int)(0xFFFFFFFFu - (unsigned)(kv[c] & 0xFFFFFFFFu));
                float val = unsortable_f((unsigned)(kv[c] >> 32));
                g_fs[((size_t)h*TOK + tok)*TOPK + s] = 1.f/(1.f + expf(-val));
                g_fidx[((size_t)h*TOK + tok)*TOPK + s] = ridx[p >> 5]*NKEY + cidx[p & 31];
            }
        }
        __syncthreads();
    }
}

__global__ __launch_bounds__(512) void gather_kernel(const float* __restrict__ mem,
                                                     float* __restrict__ out)
{
    int tok = blockIdx.x, tid = threadIdx.x;
    int h = tid >> 8, sub = (tid >> 7) & 1, t = tid & 127;
    __shared__ float w[2][TOPK];
    __shared__ int   id[2][TOPK];
    __shared__ float4 part[2][128];
    if (tid < 64){
        int hh = tid >> 5, k = tid & 31;
        w[hh][k]  = g_fs[((size_t)hh*TOK + tok)*TOPK + k];
        id[hh][k] = g_fidx[((size_t)hh*TOK + tok)*TOPK + k];
    }
    __syncthreads();
    float4 acc = {0.f,0.f,0.f,0.f};
    #pragma unroll
    for (int kk = 0; kk < 16; kk++){
        int k = sub*16 + kk;
        const float4* row = (const float4*)(mem + (size_t)id[h][k]*DV);
        float4 v = __ldg(row + t);
        float ww = w[h][k];
        acc.x += ww*v.x; acc.y += ww*v.y; acc.z += ww*v.z; acc.w += ww*v.w;
    }
    if (sub == 0) part[h][t] = acc;
    __syncthreads();
    if (sub == 1){
        float4 p = part[h][t];
        acc.x += p.x; acc.y += p.y; acc.z += p.z; acc.w += p.w;
        ((float4*)(out + (size_t)tok*1024 + h*DV))[t] = acc;
    }
}

extern "C" void kernel_launch(void* const* d_in, const int* in_sizes, int n_in,
                              void* d_out, int out_size)
{
    const float* tokens  = (const float*)d_in[0];
    const float* rms_w   = (const float*)d_in[1];
    const float* conv_w  = (const float*)d_in[2];
    const float* conv_b  = (const float*)d_in[3];
    const float* wq      = (const float*)d_in[4];
    const float* qln_w   = (const float*)d_in[5];
    const float* keys    = (const float*)d_in[6];
    const float* core    = (const float*)d_in[7];
    const float* mems    = (const float*)d_in[8];
    float* out = (float*)d_out;

    float* qpart; cudaGetSymbolAddress((void**)&qpart, g_qpart);
    float* x2;    cudaGetSymbolAddress((void**)&x2, g_x2);
    float* sc;    cudaGetSymbolAddress((void**)&sc, g_sc);

    ksplit_kernel<<<(1024*DQK)/256, 256>>>(keys);
    rms_kernel<<<TOK, 256>>>(tokens);
    conv_kernel<<<(TOK/4*DIM)/256, 256>>>(tokens, rms_w, conv_w, conv_b);
    gemm_q<<<dim3(2,16,4), 256>>>(x2, wq, qpart);
    ln_kernel<<<TOK, 128>>>(qln_w);
    gemm_sc_mma<<<dim3(16,16), 256>>>(sc);
    select_kernel<<<TOK, 256>>>(core, out, out_size);
    gather_kernel<<<TOK, 512>>>(mems, out);
}

// round 10
// speedup vs baseline: 1.0977x; 1.0977x over previous
#include <cuda_runtime.h>
#include <cuda_bf16.h>
#include <math.h>

#define BB 2
#define NN 1024
#define TOK (BB*NN)
#define DIM 1024
#define DQK 128
#define NKEY 256
#define TOPK 32
#define DV 512
#define KCONV 5
#define OUT_MAIN (TOK*1024)
#define NSEG 6
#define KTILES (NSEG*8)   // K' = 6*128 = 768 -> 48 ktiles of 16

__device__ float g_invrms[TOK];
__device__ float g_x2[TOK*DIM];
__device__ float g_qpart[8*TOK*DQK];
__device__ float g_sc[TOK*1024];
__device__ float g_fs[2*TOK*TOPK];
__device__ int   g_fidx[2*TOK*TOPK];
// fragment-packed bf16 operands for the score GEMM (paired split segments)
// A: [mtile(128)][ktile(48)][lane*4+reg] (u32 = 2 bf16)
// B: [ntile(128)][ktile(48)][lane*2+reg]
__device__ unsigned g_Apack[128*KTILES*128];
__device__ unsigned g_Bpack[128*KTILES*64];

__device__ __forceinline__ float fsign(float a, float b){ return (b >= 0.f) ? fabsf(a) : -fabsf(a); }
__device__ __forceinline__ unsigned sortable_f(float f){
    unsigned u = __float_as_uint(f);
    return (u & 0x80000000u) ? ~u : (u | 0x80000000u);
}
__device__ __forceinline__ float unsortable_f(unsigned s){
    unsigned u = (s & 0x80000000u) ? (s ^ 0x80000000u) : ~s;
    return __uint_as_float(u);
}
__device__ __forceinline__ unsigned long long pack_key(float v, unsigned idx){
    return (((unsigned long long)sortable_f(v)) << 32) | (unsigned long long)(0xFFFFFFFFu - idx);
}

// ---------------- LAPACK slasv2 port ----------------
__device__ void slasv2_dev(float f, float g, float h,
                           float& ssmin, float& ssmax,
                           float& snr, float& csr, float& snl, float& csl)
{
    float ft=f, fa=fabsf(f), ht=h, ha=fabsf(h);
    int pmax = 1;
    bool swp = (ha > fa);
    if (swp){ pmax = 3; float t; t=ft; ft=ht; ht=t; t=fa; fa=ha; ha=t; }
    float gt=g, ga=fabsf(g);
    float clt=0.f, crt=0.f, slt=0.f, srt=0.f;
    if (ga == 0.f){
        ssmin = ha; ssmax = fa; clt=1.f; crt=1.f; slt=0.f; srt=0.f;
    } else {
        bool gasmal = true;
        if (ga > fa){
            pmax = 2;
            if ((fa/ga) < 5.9604645e-08f){
                gasmal = false;
                ssmax = ga;
                ssmin = (ha > 1.f) ? (fa/(ga/ha)) : ((fa/ga)*ha);
                clt = 1.f; slt = ht/gt; srt = 1.f; crt = ft/gt;
            }
        }
        if (gasmal){
            float d_ = fa - ha;
            float l  = (d_ == fa) ? 1.f : d_/fa;
            float m  = gt/ft;
            float t  = 2.f - l;
            float mm = m*m, tt = t*t;
            float s  = sqrtf(tt + mm);
            float r_ = (l == 0.f) ? fabsf(m) : sqrtf(l*l + mm);
            float a_ = 0.5f*(s + r_);
            ssmin = ha/a_;
            ssmax = fa*a_;
            if (mm == 0.f){
                t = (l == 0.f) ? (fsign(2.f, ft)*fsign(1.f, gt))
                               : (gt/fsign(d_, ft) + m/t);
            } else {
                t = (m/(s + t) + m/(r_ + l))*(1.f + a_);
            }
            float l2 = sqrtf(t*t + 4.f);
            crt = 2.f/l2;
            srt = t/l2;
            clt = (crt + srt*m)/a_;
            slt = (ht/ft)*srt/a_;
        }
    }
    if (swp){ csl = srt; snl = crt; csr = slt; snr = clt; }
    else    { csl = clt; snl = slt; csr = crt; snr = srt; }
    float ts = 0.f;
    if (pmax == 1) ts = fsign(1.f, csr)*fsign(1.f, csl)*fsign(1.f, f);
    if (pmax == 2) ts = fsign(1.f, snr)*fsign(1.f, csl)*fsign(1.f, g);
    if (pmax == 3) ts = fsign(1.f, snr)*fsign(1.f, snl)*fsign(1.f, h);
    ssmax = fsign(ssmax, ts);
    ssmin = fsign(ssmin, ts*fsign(1.f, f)*fsign(1.f, h));
}

__device__ void svd2x2(const float* core, int hh, float& u0, float& u1,
                       float& t0, float& t1, float& auxp)
{
    float a = core[hh*4+0], b = core[hh*4+1];
    float c = core[hh*4+2], d = core[hh*4+3];
    float q00=1.f,q01=0.f,q10=0.f,q11=1.f;
    float d1, e1, d2;
    if (c != 0.f){
        float nrm  = sqrtf(a*a + c*c);
        float beta = (a >= 0.f) ? -nrm : nrm;
        float tau  = (beta - a)/beta;
        float v    = c/(a - beta);
        float w    = b + v*d;
        e1 = b - tau*w;
        d2 = d - tau*v*w;
        d1 = beta;
        q00 = 1.f - tau; q01 = -tau*v; q10 = -tau*v; q11 = 1.f - tau*v*v;
    } else { d1 = a; e1 = b; d2 = d; }
    float ssmin, ssmax, snr, csr, snl, csl;
    slasv2_dev(d1, e1, d2, ssmin, ssmax, snr, csr, snl, csl);
    float vt0 = csr, vt1 = snr;
    float s1 = ssmax;
    if (s1 < 0.f){ s1 = -s1; vt0 = -vt0; vt1 = -vt1; }
    float s2 = fabsf(ssmin);
    u0 = q00*csl + q01*snl;
    u1 = q10*csl + q11*snl;
    t0 = vt0;
    t1 = vt1;
    float r = s2 - 0.15f;
    auxp = (r > 0.f) ? r*r : 0.f;
}

__global__ void rms_kernel(const float* __restrict__ tokens)
{
    int tok = blockIdx.x;
    const float4* p = (const float4*)(tokens + (size_t)tok*DIM);
    float4 v = p[threadIdx.x];
    float s = v.x*v.x + v.y*v.y + v.z*v.z + v.w*v.w;
    for (int o = 16; o; o >>= 1) s += __shfl_xor_sync(0xFFFFFFFFu, s, o);
    __shared__ float ws[8];
    if ((threadIdx.x & 31) == 0) ws[threadIdx.x >> 5] = s;
    __syncthreads();
    if (threadIdx.x == 0){
        float t = 0.f;
        #pragma unroll
        for (int i = 0; i < 8; i++) t += ws[i];
        g_invrms[tok] = rsqrtf(t*(1.f/1024.f) + 1.1920929e-07f);
    }
}

__global__ void conv_kernel(const float* __restrict__ tokens,
                            const float* __restrict__ rms_w,
                            const float* __restrict__ conv_w,
                            const float* __restrict__ conv_b)
{
    int gid = blockIdx.x*256 + threadIdx.x;
    int d   = gid & (DIM-1);
    int grp = gid >> 10;
    int ng  = grp & (NN/4 - 1);
    int bb  = grp >> 8;
    float rw = rms_w[d];
    float wv[KCONV];
    #pragma unroll
    for (int k = 0; k < KCONV; k++) wv[k] = conv_w[d*KCONV + k];
    float xv[8];
    #pragma unroll
    for (int j = 0; j < 8; j++){
        int nn = ng*4 - 4 + j;
        if (nn >= 0){
            int t2 = (bb << 10) + nn;
            xv[j] = tokens[(size_t)t2*DIM + d] * g_invrms[t2] * rw;
        } else xv[j] = 0.f;
    }
    float cb = conv_b[d];
    #pragma unroll
    for (int i = 0; i < 4; i++){
        float acc = cb;
        #pragma unroll
        for (int k = 0; k < KCONV; k++) acc += wv[k]*xv[i+k];
        g_x2[(size_t)((bb << 10) + ng*4 + i)*DIM + d] = acc;
    }
}

// GEMM1: qpart[z] = x2 @ wq^T, split-K=8 (proven best config)
__global__ __launch_bounds__(256) void gemm_q(const float* __restrict__ A,
                                              const float* __restrict__ B,
                                              float* __restrict__ C)
{
    __shared__ float As[2][16][132];
    __shared__ float Bs[2][16][68];
    int tid = threadIdx.x, tx = tid & 15, ty = tid >> 4;
    int m0 = blockIdx.y*128, n0 = blockIdx.x*64, k0 = blockIdx.z*128;
    C += (size_t)blockIdx.z*(TOK*DQK);
    const float* Ab = A + (size_t)m0*DIM + k0;
    const float* Bb = B + (size_t)n0*DIM + k0;
    float acc[8][4];
    #pragma unroll
    for (int i = 0; i < 8; i++)
        #pragma unroll
        for (int j = 0; j < 4; j++) acc[i][j] = 0.f;
    float ra[8], rb[4];
    #pragma unroll
    for (int e = 0; e < 8; e++){ int f = tid + e*256; ra[e] = Ab[(size_t)(f >> 4)*DIM + (f & 15)]; }
    #pragma unroll
    for (int e = 0; e < 4; e++){ int f = tid + e*256; rb[e] = Bb[(size_t)(f >> 4)*DIM + (f & 15)]; }
    #pragma unroll
    for (int e = 0; e < 8; e++){ int f = tid + e*256; As[0][f & 15][f >> 4] = ra[e]; }
    #pragma unroll
    for (int e = 0; e < 4; e++){ int f = tid + e*256; Bs[0][f & 15][f >> 4] = rb[e]; }
    __syncthreads();
    int cur = 0;
    for (int kk = 0; kk < 128; kk += 16){
        bool nxt = (kk + 16) < 128;
        if (nxt){
            #pragma unroll
            for (int e = 0; e < 8; e++){ int f = tid + e*256; ra[e] = Ab[(size_t)(f >> 4)*DIM + kk + 16 + (f & 15)]; }
            #pragma unroll
            for (int e = 0; e < 4; e++){ int f = tid + e*256; rb[e] = Bb[(size_t)(f >> 4)*DIM + kk + 16 + (f & 15)]; }
        }
        #pragma unroll
        for (int k = 0; k < 16; k++){
            float4 a0 = *(const float4*)&As[cur][k][ty*8];
            float4 a1 = *(const float4*)&As[cur][k][ty*8+4];
            float4 b0 = *(const float4*)&Bs[cur][k][tx*4];
            float a[8] = {a0.x,a0.y,a0.z,a0.w,a1.x,a1.y,a1.z,a1.w};
            float b[4] = {b0.x,b0.y,b0.z,b0.w};
            #pragma unroll
            for (int i = 0; i < 8; i++)
                #pragma unroll
                for (int j = 0; j < 4; j++)
                    acc[i][j] += a[i]*b[j];
        }
        if (nxt){
            #pragma unroll
            for (int e = 0; e < 8; e++){ int f = tid + e*256; As[cur^1][f & 15][f >> 4] = ra[e]; }
            #pragma unroll
            for (int e = 0; e < 4; e++){ int f = tid + e*256; Bs[cur^1][f & 15][f >> 4] = rb[e]; }
            __syncthreads();
            cur ^= 1;
        }
    }
    #pragma unroll
    for (int i = 0; i < 8; i++){
        float4 v = {acc[i][0], acc[i][1], acc[i][2], acc[i][3]};
        *(float4*)(C + (size_t)(m0 + ty*8 + i)*DQK + n0 + tx*4) = v;
    }
}

// packed writers (verified against PTX m16n8k16 fragment layout)
__device__ __forceinline__ void apack_store(int m, int k, __nv_bfloat16 v){
    int mtile = m >> 4, ktile = k >> 4;
    int ml = m & 15, kl = k & 15;
    int lane = (ml & 7)*4 + ((kl & 7) >> 1);
    int reg  = (ml >> 3) + 2*(kl >> 3);
    size_t u = ((size_t)(mtile*KTILES + ktile))*128 + lane*4 + reg;
    ((__nv_bfloat16*)g_Apack)[u*2 + (kl & 1)] = v;
}
__device__ __forceinline__ void bpack_store(int n, int k, __nv_bfloat16 v){
    int ntile = n >> 3, ktile = k >> 4;
    int nl = n & 7, kl = k & 15;
    int lane = nl*4 + ((kl & 7) >> 1);
    int reg  = kl >> 3;
    size_t u = ((size_t)(ntile*KTILES + ktile))*64 + lane*2 + reg;
    ((__nv_bfloat16*)g_Bpack)[u*2 + (kl & 1)] = v;
}

// segment plane pairing: product s computes Aplane[pa[s]] . Bplane[pb[s]]
// {hh, hm, mh, mm, hl, lh} — dropped ml/lm/ll ~2^-27 relative.
__constant__ int c_pa[NSEG] = {0,0,1,1,0,2};
__constant__ int c_pb[NSEG] = {0,1,0,1,2,0};

// sum split-K partials + LayerNorm + emit paired split segments into packed A
__global__ void ln_kernel(const float* __restrict__ qln_w)
{
    int tok = blockIdx.x, t = threadIdx.x;
    float v = 0.f;
    #pragma unroll
    for (int z = 0; z < 8; z++) v += g_qpart[(size_t)z*TOK*DQK + tok*DQK + t];
    float s = v;
    for (int o = 16; o; o >>= 1) s += __shfl_xor_sync(0xFFFFFFFFu, s, o);
    __shared__ float ws[4], ws2[4];
    int w = t >> 5, l = t & 31;
    if (l == 0) ws[w] = s;
    __syncthreads();
    float mu = (ws[0]+ws[1]+ws[2]+ws[3]) * (1.f/128.f);
    float dv = v - mu;
    float s2 = dv*dv;
    for (int o = 16; o; o >>= 1) s2 += __shfl_xor_sync(0xFFFFFFFFu, s2, o);
    if (l == 0) ws2[w] = s2;
    __syncthreads();
    float var = (ws2[0]+ws2[1]+ws2[2]+ws2[3]) * (1.f/128.f);
    float q = dv * rsqrtf(var + 1e-5f) * qln_w[t];
    __nv_bfloat16 pl[3];
    pl[0] = __float2bfloat16(q);
    float fh = __bfloat162float(pl[0]);
    pl[1] = __float2bfloat16(q - fh);
    float fm = __bfloat162float(pl[1]);
    pl[2] = __float2bfloat16(q - fh - fm);
    #pragma unroll
    for (int sgi = 0; sgi < NSEG; sgi++)
        apack_store(tok, sgi*128 + t, pl[c_pa[sgi]]);
}

// permute keys + paired split segments into packed B
__global__ void ksplit_kernel(const float* __restrict__ keys)
{
    int gid = blockIdx.x*256 + threadIdx.x;   // 1024*128
    int d = gid & 127, j = gid >> 7;
    int c = j >> 9, rem = j & 511, m = rem >> 1, r = rem & 1;
    float v = keys[(((c*2 + r)*NKEY + m)*DQK) + d];
    __nv_bfloat16 pl[3];
    pl[0] = __float2bfloat16(v);
    float fh = __bfloat162float(pl[0]);
    pl[1] = __float2bfloat16(v - fh);
    float fm = __bfloat162float(pl[1]);
    pl[2] = __float2bfloat16(v - fh - fm);
    #pragma unroll
    for (int sgi = 0; sgi < NSEG; sgi++)
        bpack_store(j, sgi*128 + d, pl[c_pb[sgi]]);
}

__device__ __forceinline__ void mma16816(float* d, const unsigned* a, const unsigned* b){
    asm volatile("mma.sync.aligned.m16n8k16.row.col.f32.bf16.bf16.f32 "
        "{%0,%1,%2,%3}, {%4,%5,%6,%7}, {%8,%9}, {%0,%1,%2,%3};"
        : "+f"(d[0]), "+f"(d[1]), "+f"(d[2]), "+f"(d[3])
        : "r"(a[0]), "r"(a[1]), "r"(a[2]), "r"(a[3]), "r"(b[0]), "r"(b[1]));
}

// GEMM2: sc = q @ kp^T via bf16 MMA over K'=768 paired segments, fragment-packed.
// block 256 thr = 8 warps (4m x 2n); warp tile m32 x n32; block tile M128 x N64.
__global__ __launch_bounds__(256) void gemm_sc_mma(float* __restrict__ C)
{
    int tid = threadIdx.x;
    int w = tid >> 5, lane = tid & 31;
    int g = lane >> 2, tg = lane & 3;
    int wm = w >> 1, wn = w & 1;
    int mt0 = blockIdx.y*8 + wm*2;
    int nt0 = blockIdx.x*8 + wn*4;
    const uint4* Ap = (const uint4*)g_Apack;
    const uint2* Bp = (const uint2*)g_Bpack;
    float acc[2][4][4];
    #pragma unroll
    for (int i = 0; i < 2; i++)
        #pragma unroll
        for (int j = 0; j < 4; j++)
            #pragma unroll
            for (int e = 0; e < 4; e++) acc[i][j][e] = 0.f;
    uint4 a0[2]; uint2 b0[4];
    #pragma unroll
    for (int mt = 0; mt < 2; mt++) a0[mt] = Ap[((size_t)(mt0+mt)*KTILES + 0)*32 + lane];
    #pragma unroll
    for (int nt = 0; nt < 4; nt++) b0[nt] = Bp[((size_t)(nt0+nt)*KTILES + 0)*32 + lane];
    for (int kt = 0; kt < KTILES; kt++){
        uint4 a1[2]; uint2 b1[4];
        if (kt + 1 < KTILES){
            #pragma unroll
            for (int mt = 0; mt < 2; mt++) a1[mt] = Ap[((size_t)(mt0+mt)*KTILES + kt + 1)*32 + lane];
            #pragma unroll
            for (int nt = 0; nt < 4; nt++) b1[nt] = Bp[((size_t)(nt0+nt)*KTILES + kt + 1)*32 + lane];
        }
        #pragma unroll
        for (int mt = 0; mt < 2; mt++){
            unsigned af[4] = {a0[mt].x, a0[mt].y, a0[mt].z, a0[mt].w};
            #pragma unroll
            for (int nt = 0; nt < 4; nt++){
                unsigned bf[2] = {b0[nt].x, b0[nt].y};
                mma16816(acc[mt][nt], af, bf);
            }
        }
        if (kt + 1 < KTILES){
            #pragma unroll
            for (int mt = 0; mt < 2; mt++) a0[mt] = a1[mt];
            #pragma unroll
            for (int nt = 0; nt < 4; nt++) b0[nt] = b1[nt];
        }
    }
    int m0 = blockIdx.y*128 + wm*32;
    int n0 = blockIdx.x*64 + wn*32;
    #pragma unroll
    for (int mt = 0; mt < 2; mt++){
        #pragma unroll
        for (int nt = 0; nt < 4; nt++){
            int row = m0 + mt*16 + g;
            int col = n0 + nt*8 + tg*2;
            float2 v0 = {acc[mt][nt][0], acc[mt][nt][1]};
            float2 v1 = {acc[mt][nt][2], acc[mt][nt][3]};
            *(float2*)(C + (size_t)row*1024 + col) = v0;
            *(float2*)(C + (size_t)(row+8)*1024 + col) = v1;
        }
    }
}

// ---------------- block-wide exact top-32 threshold via MSB radix descent ----------------
__device__ unsigned long long radix_select32(const unsigned long long* kv, int npt, int tid,
                                             unsigned* hist, unsigned* sh)
{
    unsigned long long prefix = 0;
    bool act[4] = {true, true, true, true};
    int need = 32;
    int lane = tid & 31, w = tid >> 5;
    for (int shift = 56; shift >= 0; shift -= 8){
        hist[tid] = 0;
        __syncthreads();
        #pragma unroll
        for (int e = 0; e < 4; e++)
            if (e < npt && act[e])
                atomicAdd(&hist[(unsigned)((kv[e] >> shift) & 255)], 1u);
        __syncthreads();
        unsigned h = hist[tid];
        unsigned inc = h;
        #pragma unroll
        for (int off = 1; off < 32; off <<= 1){
            unsigned v = __shfl_down_sync(0xFFFFFFFFu, inc, off);
            if (lane + off < 32) inc += v;
        }
        if (lane == 0) sh[8 + w] = inc;
        __syncthreads();
        unsigned upper = 0;
        #pragma unroll
        for (int ww = 1; ww < 8; ww++) if (ww > w) upper += sh[8 + ww];
        unsigned cge = inc + upper;
        unsigned cgt = cge - h;
        if (cgt < (unsigned)need && cge >= (unsigned)need){
            sh[0] = (unsigned)tid;
            sh[1] = (unsigned)need - cgt;
            sh[2] = (h == (unsigned)need - cgt) ? 1u : 0u;
        }
        __syncthreads();
        unsigned D = sh[0];
        need = (int)sh[1];
        unsigned done = sh[2];
        prefix |= ((unsigned long long)D) << shift;
        if (done) return prefix;
        #pragma unroll
        for (int e = 0; e < 4; e++)
            if (e < npt)
                act[e] = act[e] && (((kv[e] >> shift) & 255) == (unsigned long long)D);
        __syncthreads();
    }
    return prefix;
}

__global__ __launch_bounds__(256) void select_kernel(const float* __restrict__ core,
                                                     float* __restrict__ d_out, int out_size)
{
    __shared__ float rs[1024];
    __shared__ unsigned hist[256];
    __shared__ unsigned sh[16];
    __shared__ int ridx[32], cidx[32];
    __shared__ float gg0[32], gg1[32], fc0[32], fc1[32];
    __shared__ float suv[8];
    __shared__ int cnt;
    int tok = blockIdx.x, tid = threadIdx.x;
    if (tid == 0){
        float aux = 0.f;
        #pragma unroll
        for (int hh = 0; hh < 2; hh++){
            float u0,u1,t0,t1,ap;
            svd2x2(core, hh, u0, u1, t0, t1, ap);
            suv[hh*4+0]=u0; suv[hh*4+1]=u1; suv[hh*4+2]=t0; suv[hh*4+3]=t1;
            aux += ap;
        }
        if (tok == 0 && out_size > OUT_MAIN) d_out[OUT_MAIN] = aux*0.1f;
    }
    #pragma unroll
    for (int e = 0; e < 4; e++) rs[tid + e*256] = g_sc[(size_t)tok*1024 + tid + e*256];
    __syncthreads();

    for (int h = 0; h < 2; h++){
        float u0 = suv[h*4+0], u1 = suv[h*4+1];
        float t0 = suv[h*4+2], t1 = suv[h*4+3];
        float c00 = core[h*4+0], c01 = core[h*4+1], c10 = core[h*4+2], c11 = core[h*4+3];

        if (tid == 0) cnt = 0;
        unsigned long long kr = pack_key(rs[2*tid]*u0 + rs[2*tid+1]*u1, (unsigned)tid);
        unsigned long long T = radix_select32(&kr, 1, tid, hist, sh);
        if (kr >= T){ int s = atomicAdd(&cnt, 1); ridx[s] = tid; }
        __syncthreads();
        if (tid < 32){
            int mi = ridx[tid];
            float f0 = rs[2*mi], f1 = rs[2*mi+1];
            gg0[tid] = f0*c00 + f1*c10;
            gg1[tid] = f0*c01 + f1*c11;
        }

        if (tid == 0) cnt = 0;
        unsigned long long kc = pack_key(rs[512 + 2*tid]*t0 + rs[512 + 2*tid+1]*t1, (unsigned)tid);
        T = radix_select32(&kc, 1, tid, hist, sh);
        if (kc >= T){ int s = atomicAdd(&cnt, 1); cidx[s] = tid; }
        __syncthreads();
        if (tid < 32){
            int mi = cidx[tid];
            fc0[tid] = rs[512 + 2*mi];
            fc1[tid] = rs[512 + 2*mi+1];
        }
        __syncthreads();

        if (tid == 0) cnt = 0;
        unsigned long long kv[4];
        #pragma unroll
        for (int c = 0; c < 4; c++){
            int p = c*256 + tid;
            int i = p >> 5, j = p & 31;
            float val = gg0[i]*fc0[j] + gg1[i]*fc1[j];
            kv[c] = pack_key(val, (unsigned)p);
        }
        T = radix_select32(kv, 4, tid, hist, sh);
        #pragma unroll
        for (int c = 0; c < 4; c++){
            if (kv[c] >= T){
                int s = atomicAdd(&cnt, 1);
                int p = (int)(0xFFFFFFFFu - (unsigned)(kv[c] & 0xFFFFFFFFu));
                float val = unsortable_f((unsigned)(kv[c] >> 32));
                g_fs[((size_t)h*TOK + tok)*TOPK + s] = 1.f/(1.f + expf(-val));
                g_fidx[((size_t)h*TOK + tok)*TOPK + s] = ridx[p >> 5]*NKEY + cidx[p & 31];
            }
        }
        __syncthreads();
    }
}

__global__ __launch_bounds__(512) void gather_kernel(const float* __restrict__ mem,
                                                     float* __restrict__ out)
{
    int tok = blockIdx.x, tid = threadIdx.x;
    int h = tid >> 8, sub = (tid >> 7) & 1, t = tid & 127;
    __shared__ float w[2][TOPK];
    __shared__ int   id[2][TOPK];
    __shared__ float4 part[2][128];
    if (tid < 64){
        int hh = tid >> 5, k = tid & 31;
        w[hh][k]  = g_fs[((size_t)hh*TOK + tok)*TOPK + k];
        id[hh][k] = g_fidx[((size_t)hh*TOK + tok)*TOPK + k];
    }
    __syncthreads();
    float4 acc = {0.f,0.f,0.f,0.f};
    #pragma unroll
    for (int kk = 0; kk < 16; kk++){
        int k = sub*16 + kk;
        const float4* row = (const float4*)(mem + (size_t)id[h][k]*DV);
        float4 v = __ldg(row + t);
        float ww = w[h][k];
        acc.x += ww*v.x; acc.y += ww*v.y; acc.z += ww*v.z; acc.w += ww*v.w;
    }
    if (sub == 0) part[h][t] = acc;
    __syncthreads();
    if (sub == 1){
        float4 p = part[h][t];
        acc.x += p.x; acc.y += p.y; acc.z += p.z; acc.w += p.w;
        ((float4*)(out + (size_t)tok*1024 + h*DV))[t] = acc;
    }
}

extern "C" void kernel_launch(void* const* d_in, const int* in_sizes, int n_in,
                              void* d_out, int out_size)
{
    const float* tokens  = (const float*)d_in[0];
    const float* rms_w   = (const float*)d_in[1];
    const float* conv_w  = (const float*)d_in[2];
    const float* conv_b  = (const float*)d_in[3];
    const float* wq      = (const float*)d_in[4];
    const float* qln_w   = (const float*)d_in[5];
    const float* keys    = (const float*)d_in[6];
    const float* core    = (const float*)d_in[7];
    const float* mems    = (const float*)d_in[8];
    float* out = (float*)d_out;

    float* qpart; cudaGetSymbolAddress((void**)&qpart, g_qpart);
    float* x2;    cudaGetSymbolAddress((void**)&x2, g_x2);
    float* sc;    cudaGetSymbolAddress((void**)&sc, g_sc);

    ksplit_kernel<<<(1024*DQK)/256, 256>>>(keys);
    rms_kernel<<<TOK, 256>>>(tokens);
    conv_kernel<<<(TOK/4*DIM)/256, 256>>>(tokens, rms_w, conv_w, conv_b);
    gemm_q<<<dim3(2,16,8), 256>>>(x2, wq, qpart);
    ln_kernel<<<TOK, 128>>>(qln_w);
    gemm_sc_mma<<<dim3(16,16), 256>>>(sc);
    select_kernel<<<TOK, 256>>>(core, out, out_size);
    gather_kernel<<<TOK, 512>>>(mems, out);
}

// round 11
// speedup vs baseline: 1.1722x; 1.0678x over previous
#include <cuda_runtime.h>
#include <cuda_bf16.h>
#include <math.h>

#define BB 2
#define NN 1024
#define TOK (BB*NN)
#define DIM 1024
#define DQK 128
#define NKEY 256
#define TOPK 32
#define DV 512
#define KCONV 5
#define OUT_MAIN (TOK*1024)

__device__ float g_invrms[TOK];
__device__ float g_x2[TOK*DIM];
__device__ float g_qpart[8*TOK*DQK];
__device__ float g_q[TOK*DQK];
__device__ float g_sc[TOK*1024];
__device__ float g_fs[2*TOK*TOPK];
__device__ int   g_fidx[2*TOK*TOPK];

__device__ __forceinline__ float fsign(float a, float b){ return (b >= 0.f) ? fabsf(a) : -fabsf(a); }
__device__ __forceinline__ unsigned sortable_f(float f){
    unsigned u = __float_as_uint(f);
    return (u & 0x80000000u) ? ~u : (u | 0x80000000u);
}
__device__ __forceinline__ float unsortable_f(unsigned s){
    unsigned u = (s & 0x80000000u) ? (s ^ 0x80000000u) : ~s;
    return __uint_as_float(u);
}
__device__ __forceinline__ unsigned long long pack_key(float v, unsigned idx){
    return (((unsigned long long)sortable_f(v)) << 32) | (unsigned long long)(0xFFFFFFFFu - idx);
}

// ---------------- LAPACK slasv2 port ----------------
__device__ void slasv2_dev(float f, float g, float h,
                           float& ssmin, float& ssmax,
                           float& snr, float& csr, float& snl, float& csl)
{
    float ft=f, fa=fabsf(f), ht=h, ha=fabsf(h);
    int pmax = 1;
    bool swp = (ha > fa);
    if (swp){ pmax = 3; float t; t=ft; ft=ht; ht=t; t=fa; fa=ha; ha=t; }
    float gt=g, ga=fabsf(g);
    float clt=0.f, crt=0.f, slt=0.f, srt=0.f;
    if (ga == 0.f){
        ssmin = ha; ssmax = fa; clt=1.f; crt=1.f; slt=0.f; srt=0.f;
    } else {
        bool gasmal = true;
        if (ga > fa){
            pmax = 2;
            if ((fa/ga) < 5.9604645e-08f){
                gasmal = false;
                ssmax = ga;
                ssmin = (ha > 1.f) ? (fa/(ga/ha)) : ((fa/ga)*ha);
                clt = 1.f; slt = ht/gt; srt = 1.f; crt = ft/gt;
            }
        }
        if (gasmal){
            float d_ = fa - ha;
            float l  = (d_ == fa) ? 1.f : d_/fa;
            float m  = gt/ft;
            float t  = 2.f - l;
            float mm = m*m, tt = t*t;
            float s  = sqrtf(tt + mm);
            float r_ = (l == 0.f) ? fabsf(m) : sqrtf(l*l + mm);
            float a_ = 0.5f*(s + r_);
            ssmin = ha/a_;
            ssmax = fa*a_;
            if (mm == 0.f){
                t = (l == 0.f) ? (fsign(2.f, ft)*fsign(1.f, gt))
                               : (gt/fsign(d_, ft) + m/t);
            } else {
                t = (m/(s + t) + m/(r_ + l))*(1.f + a_);
            }
            float l2 = sqrtf(t*t + 4.f);
            crt = 2.f/l2;
            srt = t/l2;
            clt = (crt + srt*m)/a_;
            slt = (ht/ft)*srt/a_;
        }
    }
    if (swp){ csl = srt; snl = crt; csr = slt; snr = clt; }
    else    { csl = clt; snl = slt; csr = crt; snr = srt; }
    float ts = 0.f;
    if (pmax == 1) ts = fsign(1.f, csr)*fsign(1.f, csl)*fsign(1.f, f);
    if (pmax == 2) ts = fsign(1.f, snr)*fsign(1.f, csl)*fsign(1.f, g);
    if (pmax == 3) ts = fsign(1.f, snr)*fsign(1.f, snl)*fsign(1.f, h);
    ssmax = fsign(ssmax, ts);
    ssmin = fsign(ssmin, ts*fsign(1.f, f)*fsign(1.f, h));
}

__device__ void svd2x2(const float* core, int hh, float& u0, float& u1,
                       float& t0, float& t1, float& auxp)
{
    float a = core[hh*4+0], b = core[hh*4+1];
    float c = core[hh*4+2], d = core[hh*4+3];
    float q00=1.f,q01=0.f,q10=0.f,q11=1.f;
    float d1, e1, d2;
    if (c != 0.f){
        float nrm  = sqrtf(a*a + c*c);
        float beta = (a >= 0.f) ? -nrm : nrm;
        float tau  = (beta - a)/beta;
        float v    = c/(a - beta);
        float w    = b + v*d;
        e1 = b - tau*w;
        d2 = d - tau*v*w;
        d1 = beta;
        q00 = 1.f - tau; q01 = -tau*v; q10 = -tau*v; q11 = 1.f - tau*v*v;
    } else { d1 = a; e1 = b; d2 = d; }
    float ssmin, ssmax, snr, csr, snl, csl;
    slasv2_dev(d1, e1, d2, ssmin, ssmax, snr, csr, snl, csl);
    float vt0 = csr, vt1 = snr;
    float s1 = ssmax;
    if (s1 < 0.f){ s1 = -s1; vt0 = -vt0; vt1 = -vt1; }
    float s2 = fabsf(ssmin);
    u0 = q00*csl + q01*snl;
    u1 = q10*csl + q11*snl;
    t0 = vt0;
    t1 = vt1;
    float r = s2 - 0.15f;
    auxp = (r > 0.f) ? r*r : 0.f;
}

__global__ void rms_kernel(const float* __restrict__ tokens)
{
    int tok = blockIdx.x;
    const float4* p = (const float4*)(tokens + (size_t)tok*DIM);
    float4 v = p[threadIdx.x];
    float s = v.x*v.x + v.y*v.y + v.z*v.z + v.w*v.w;
    for (int o = 16; o; o >>= 1) s += __shfl_xor_sync(0xFFFFFFFFu, s, o);
    __shared__ float ws[8];
    if ((threadIdx.x & 31) == 0) ws[threadIdx.x >> 5] = s;
    __syncthreads();
    if (threadIdx.x == 0){
        float t = 0.f;
        #pragma unroll
        for (int i = 0; i < 8; i++) t += ws[i];
        g_invrms[tok] = rsqrtf(t*(1.f/1024.f) + 1.1920929e-07f);
    }
}

__global__ void conv_kernel(const float* __restrict__ tokens,
                            const float* __restrict__ rms_w,
                            const float* __restrict__ conv_w,
                            const float* __restrict__ conv_b)
{
    int gid = blockIdx.x*256 + threadIdx.x;
    int d   = gid & (DIM-1);
    int grp = gid >> 10;
    int ng  = grp & (NN/4 - 1);
    int bb  = grp >> 8;
    float rw = rms_w[d];
    float wv[KCONV];
    #pragma unroll
    for (int k = 0; k < KCONV; k++) wv[k] = conv_w[d*KCONV + k];
    float xv[8];
    #pragma unroll
    for (int j = 0; j < 8; j++){
        int nn = ng*4 - 4 + j;
        if (nn >= 0){
            int t2 = (bb << 10) + nn;
            xv[j] = tokens[(size_t)t2*DIM + d] * g_invrms[t2] * rw;
        } else xv[j] = 0.f;
    }
    float cb = conv_b[d];
    #pragma unroll
    for (int i = 0; i < 4; i++){
        float acc = cb;
        #pragma unroll
        for (int k = 0; k < KCONV; k++) acc += wv[k]*xv[i+k];
        g_x2[(size_t)((bb << 10) + ng*4 + i)*DIM + d] = acc;
    }
}

// GEMM1: qpart[z] = x2 @ wq^T, split-K=8.  Tile M64 x N128, 256 thr, 8x4 acc.
__global__ __launch_bounds__(256) void gemm_q(const float* __restrict__ A,
                                              const float* __restrict__ B,
                                              float* __restrict__ C)
{
    __shared__ float As[2][16][68];
    __shared__ float Bs[2][16][132];
    int tid = threadIdx.x, tx = tid & 31, ty = tid >> 5;
    int m0 = blockIdx.y*64, k0 = blockIdx.z*128;
    C += (size_t)blockIdx.z*(TOK*DQK);
    const float* Ab = A + (size_t)m0*DIM + k0;
    const float* Bb = B + k0;
    float acc[8][4];
    #pragma unroll
    for (int i = 0; i < 8; i++)
        #pragma unroll
        for (int j = 0; j < 4; j++) acc[i][j] = 0.f;
    float ra[4], rb[8];
    #pragma unroll
    for (int e = 0; e < 4; e++){ int f = tid + e*256; ra[e] = Ab[(size_t)(f >> 4)*DIM + (f & 15)]; }
    #pragma unroll
    for (int e = 0; e < 8; e++){ int f = tid + e*256; rb[e] = Bb[(size_t)(f >> 4)*DIM + (f & 15)]; }
    #pragma unroll
    for (int e = 0; e < 4; e++){ int f = tid + e*256; As[0][f & 15][f >> 4] = ra[e]; }
    #pragma unroll
    for (int e = 0; e < 8; e++){ int f = tid + e*256; Bs[0][f & 15][f >> 4] = rb[e]; }
    __syncthreads();
    int cur = 0;
    for (int kk = 0; kk < 128; kk += 16){
        bool nxt = (kk + 16) < 128;
        if (nxt){
            #pragma unroll
            for (int e = 0; e < 4; e++){ int f = tid + e*256; ra[e] = Ab[(size_t)(f >> 4)*DIM + kk + 16 + (f & 15)]; }
            #pragma unroll
            for (int e = 0; e < 8; e++){ int f = tid + e*256; rb[e] = Bb[(size_t)(f >> 4)*DIM + kk + 16 + (f & 15)]; }
        }
        #pragma unroll
        for (int k = 0; k < 16; k++){
            float4 a0 = *(const float4*)&As[cur][k][ty*8];
            float4 a1 = *(const float4*)&As[cur][k][ty*8+4];
            float4 b0 = *(const float4*)&Bs[cur][k][tx*4];
            float a[8] = {a0.x,a0.y,a0.z,a0.w,a1.x,a1.y,a1.z,a1.w};
            float b[4] = {b0.x,b0.y,b0.z,b0.w};
            #pragma unroll
            for (int i = 0; i < 8; i++)
                #pragma unroll
                for (int j = 0; j < 4; j++)
                    acc[i][j] += a[i]*b[j];
        }
        if (nxt){
            #pragma unroll
            for (int e = 0; e < 4; e++){ int f = tid + e*256; As[cur^1][f & 15][f >> 4] = ra[e]; }
            #pragma unroll
            for (int e = 0; e < 8; e++){ int f = tid + e*256; Bs[cur^1][f & 15][f >> 4] = rb[e]; }
            __syncthreads();
            cur ^= 1;
        }
    }
    #pragma unroll
    for (int i = 0; i < 8; i++){
        float4 v = {acc[i][0], acc[i][1], acc[i][2], acc[i][3]};
        *(float4*)(C + (size_t)(m0 + ty*8 + i)*DQK + tx*4) = v;
    }
}

// GEMM2: sc = q @ kp^T with fused keys permutation.  Tile M64 x N128, 8x4 acc.
__global__ __launch_bounds__(256) void gemm_sc(const float* __restrict__ A,
                                               const float* __restrict__ keys,
                                               float* __restrict__ C)
{
    __shared__ float As[2][16][68];
    __shared__ float Bs[2][16][132];
    int tid = threadIdx.x, tx = tid & 31, ty = tid >> 5;
    int m0 = blockIdx.y*64, n0 = blockIdx.x*128;
    const float* Ab = A + (size_t)m0*DQK;
    unsigned brow[8];
    #pragma unroll
    for (int e = 0; e < 8; e++){
        int f = tid + e*256;
        int j = n0 + (f >> 4);
        int c = j >> 9, rem = j & 511, m = rem >> 1, r = rem & 1;
        brow[e] = (unsigned)(((c*2 + r)*NKEY + m))*DQK;
    }
    float acc[8][4];
    #pragma unroll
    for (int i = 0; i < 8; i++)
        #pragma unroll
        for (int j = 0; j < 4; j++) acc[i][j] = 0.f;
    float ra[4], rb[8];
    #pragma unroll
    for (int e = 0; e < 4; e++){ int f = tid + e*256; ra[e] = Ab[(size_t)(f >> 4)*DQK + (f & 15)]; }
    #pragma unroll
    for (int e = 0; e < 8; e++){ int f = tid + e*256; rb[e] = keys[brow[e] + (f & 15)]; }
    #pragma unroll
    for (int e = 0; e < 4; e++){ int f = tid + e*256; As[0][f & 15][f >> 4] = ra[e]; }
    #pragma unroll
    for (int e = 0; e < 8; e++){ int f = tid + e*256; Bs[0][f & 15][f >> 4] = rb[e]; }
    __syncthreads();
    int cur = 0;
    for (int kk = 0; kk < 128; kk += 16){
        bool nxt = (kk + 16) < 128;
        if (nxt){
            #pragma unroll
            for (int e = 0; e < 4; e++){ int f = tid + e*256; ra[e] = Ab[(size_t)(f >> 4)*DQK + kk + 16 + (f & 15)]; }
            #pragma unroll
            for (int e = 0; e < 8; e++){ int f = tid + e*256; rb[e] = keys[brow[e] + kk + 16 + (f & 15)]; }
        }
        #pragma unroll
        for (int k = 0; k < 16; k++){
            float4 a0 = *(const float4*)&As[cur][k][ty*8];
            float4 a1 = *(const float4*)&As[cur][k][ty*8+4];
            float4 b0 = *(const float4*)&Bs[cur][k][tx*4];
            float a[8] = {a0.x,a0.y,a0.z,a0.w,a1.x,a1.y,a1.z,a1.w};
            float b[4] = {b0.x,b0.y,b0.z,b0.w};
            #pragma unroll
            for (int i = 0; i < 8; i++)
                #pragma unroll
                for (int j = 0; j < 4; j++)
                    acc[i][j] += a[i]*b[j];
        }
        if (nxt){
            #pragma unroll
            for (int e = 0; e < 4; e++){ int f = tid + e*256; As[cur^1][f & 15][f >> 4] = ra[e]; }
            #pragma unroll
            for (int e = 0; e < 8; e++){ int f = tid + e*256; Bs[cur^1][f & 15][f >> 4] = rb[e]; }
            __syncthreads();
            cur ^= 1;
        }
    }
    #pragma unroll
    for (int i = 0; i < 8; i++){
        float4 v = {acc[i][0], acc[i][1], acc[i][2], acc[i][3]};
        *(float4*)(C + (size_t)(m0 + ty*8 + i)*1024 + n0 + tx*4) = v;
    }
}

__global__ void ln_kernel(const float* __restrict__ qln_w)
{
    int tok = blockIdx.x, t = threadIdx.x;
    float v = 0.f;
    #pragma unroll
    for (int z = 0; z < 8; z++) v += g_qpart[(size_t)z*TOK*DQK + tok*DQK + t];
    float s = v;
    for (int o = 16; o; o >>= 1) s += __shfl_xor_sync(0xFFFFFFFFu, s, o);
    __shared__ float ws[4], ws2[4];
    int w = t >> 5, l = t & 31;
    if (l == 0) ws[w] = s;
    __syncthreads();
    float mu = (ws[0]+ws[1]+ws[2]+ws[3]) * (1.f/128.f);
    float dv = v - mu;
    float s2 = dv*dv;
    for (int o = 16; o; o >>= 1) s2 += __shfl_xor_sync(0xFFFFFFFFu, s2, o);
    if (l == 0) ws2[w] = s2;
    __syncthreads();
    float var = (ws2[0]+ws2[1]+ws2[2]+ws2[3]) * (1.f/128.f);
    g_q[tok*DQK + t] = dv * rsqrtf(var + 1e-5f) * qln_w[t];
}

// ---------------- block-wide exact top-32 threshold via MSB radix descent ----------------
__device__ unsigned long long radix_select32(const unsigned long long* kv, int npt, int tid,
                                             unsigned* hist, unsigned* sh)
{
    unsigned long long prefix = 0;
    bool act[4] = {true, true, true, true};
    int need = 32;
    int lane = tid & 31, w = tid >> 5;
    for (int shift = 56; shift >= 0; shift -= 8){
        hist[tid] = 0;
        __syncthreads();
        #pragma unroll
        for (int e = 0; e < 4; e++)
            if (e < npt && act[e])
                atomicAdd(&hist[(unsigned)((kv[e] >> shift) & 255)], 1u);
        __syncthreads();
        unsigned h = hist[tid];
        unsigned inc = h;
        #pragma unroll
        for (int off = 1; off < 32; off <<= 1){
            unsigned v = __shfl_down_sync(0xFFFFFFFFu, inc, off);
            if (lane + off < 32) inc += v;
        }
        if (lane == 0) sh[8 + w] = inc;
        __syncthreads();
        unsigned upper = 0;
        #pragma unroll
        for (int ww = 1; ww < 8; ww++) if (ww > w) upper += sh[8 + ww];
        unsigned cge = inc + upper;
        unsigned cgt = cge - h;
        if (cgt < (unsigned)need && cge >= (unsigned)need){
            sh[0] = (unsigned)tid;
            sh[1] = (unsigned)need - cgt;
            sh[2] = (h == (unsigned)need - cgt) ? 1u : 0u;
        }
        __syncthreads();
        unsigned D = sh[0];
        need = (int)sh[1];
        unsigned done = sh[2];
        prefix |= ((unsigned long long)D) << shift;
        if (done) return prefix;
        #pragma unroll
        for (int e = 0; e < 4; e++)
            if (e < npt)
                act[e] = act[e] && (((kv[e] >> shift) & 255) == (unsigned long long)D);
        __syncthreads();
    }
    return prefix;
}

__global__ __launch_bounds__(256) void select_kernel(const float* __restrict__ core,
                                                     float* __restrict__ d_out, int out_size)
{
    __shared__ float rs[1024];
    __shared__ unsigned hist[256];
    __shared__ unsigned sh[16];
    __shared__ int ridx[32], cidx[32];
    __shared__ float gg0[32], gg1[32], fc0[32], fc1[32];
    __shared__ float suv[8];
    __shared__ int cnt;
    int tok = blockIdx.x, tid = threadIdx.x;
    if (tid == 0){
        float aux = 0.f;
        #pragma unroll
        for (int hh = 0; hh < 2; hh++){
            float u0,u1,t0,t1,ap;
            svd2x2(core, hh, u0, u1, t0, t1, ap);
            suv[hh*4+0]=u0; suv[hh*4+1]=u1; suv[hh*4+2]=t0; suv[hh*4+3]=t1;
            aux += ap;
        }
        if (tok == 0 && out_size > OUT_MAIN) d_out[OUT_MAIN] = aux*0.1f;
    }
    #pragma unroll
    for (int e = 0; e < 4; e++) rs[tid + e*256] = g_sc[(size_t)tok*1024 + tid + e*256];
    __syncthreads();

    for (int h = 0; h < 2; h++){
        float u0 = suv[h*4+0], u1 = suv[h*4+1];
        float t0 = suv[h*4+2], t1 = suv[h*4+3];
        float c00 = core[h*4+0], c01 = core[h*4+1], c10 = core[h*4+2], c11 = core[h*4+3];

        if (tid == 0) cnt = 0;
        unsigned long long kr = pack_key(rs[2*tid]*u0 + rs[2*tid+1]*u1, (unsigned)tid);
        unsigned long long T = radix_select32(&kr, 1, tid, hist, sh);
        if (kr >= T){ int s = atomicAdd(&cnt, 1); ridx[s] = tid; }
        __syncthreads();
        if (tid < 32){
            int mi = ridx[tid];
            float f0 = rs[2*mi], f1 = rs[2*mi+1];
            gg0[tid] = f0*c00 + f1*c10;
            gg1[tid] = f0*c01 + f1*c11;
        }

        if (tid == 0) cnt = 0;
        unsigned long long kc = pack_key(rs[512 + 2*tid]*t0 + rs[512 + 2*tid+1]*t1, (unsigned)tid);
        T = radix_select32(&kc, 1, tid, hist, sh);
        if (kc >= T){ int s = atomicAdd(&cnt, 1); cidx[s] = tid; }
        __syncthreads();
        if (tid < 32){
            int mi = cidx[tid];
            fc0[tid] = rs[512 + 2*mi];
            fc1[tid] = rs[512 + 2*mi+1];
        }
        __syncthreads();

        if (tid == 0) cnt = 0;
        unsigned long long kv[4];
        #pragma unroll
        for (int c = 0; c < 4; c++){
            int p = c*256 + tid;
            int i = p >> 5, j = p & 31;
            float val = gg0[i]*fc0[j] + gg1[i]*fc1[j];
            kv[c] = pack_key(val, (unsigned)p);
        }
        T = radix_select32(kv, 4, tid, hist, sh);
        #pragma unroll
        for (int c = 0; c < 4; c++){
            if (kv[c] >= T){
                int s = atomicAdd(&cnt, 1);
                int p = (int)(0xFFFFFFFFu - (unsigned)(kv[c] & 0xFFFFFFFFu));
                float val = unsortable_f((unsigned)(kv[c] >> 32));
                g_fs[((size_t)h*TOK + tok)*TOPK + s] = 1.f/(1.f + expf(-val));
                g_fidx[((size_t)h*TOK + tok)*TOPK + s] = ridx[p >> 5]*NKEY + cidx[p & 31];
            }
        }
        __syncthreads();
    }
}

__global__ __launch_bounds__(512) void gather_kernel(const float* __restrict__ mem,
                                                     float* __restrict__ out)
{
    int tok = blockIdx.x, tid = threadIdx.x;
    int h = tid >> 8, sub = (tid >> 7) & 1, t = tid & 127;
    __shared__ float w[2][TOPK];
    __shared__ int   id[2][TOPK];
    __shared__ float4 part[2][128];
    if (tid < 64){
        int hh = tid >> 5, k = tid & 31;
        w[hh][k]  = g_fs[((size_t)hh*TOK + tok)*TOPK + k];
        id[hh][k] = g_fidx[((size_t)hh*TOK + tok)*TOPK + k];
    }
    __syncthreads();
    float4 acc = {0.f,0.f,0.f,0.f};
    #pragma unroll
    for (int kk = 0; kk < 16; kk++){
        int k = sub*16 + kk;
        const float4* row = (const float4*)(mem + (size_t)id[h][k]*DV);
        float4 v = __ldg(row + t);
        float ww = w[h][k];
        acc.x += ww*v.x; acc.y += ww*v.y; acc.z += ww*v.z; acc.w += ww*v.w;
    }
    if (sub == 0) part[h][t] = acc;
    __syncthreads();
    if (sub == 1){
        float4 p = part[h][t];
        acc.x += p.x; acc.y += p.y; acc.z += p.z; acc.w += p.w;
        ((float4*)(out + (size_t)tok*1024 + h*DV))[t] = acc;
    }
}

extern "C" void kernel_launch(void* const* d_in, const int* in_sizes, int n_in,
                              void* d_out, int out_size)
{
    const float* tokens  = (const float*)d_in[0];
    const float* rms_w   = (const float*)d_in[1];
    const float* conv_w  = (const float*)d_in[2];
    const float* conv_b  = (const float*)d_in[3];
    const float* wq      = (const float*)d_in[4];
    const float* qln_w   = (const float*)d_in[5];
    const float* keys    = (const float*)d_in[6];
    const float* core    = (const float*)d_in[7];
    const float* mems    = (const float*)d_in[8];
    float* out = (float*)d_out;

    float* qpart; cudaGetSymbolAddress((void**)&qpart, g_qpart);
    float* x2;    cudaGetSymbolAddress((void**)&x2, g_x2);
    float* q;     cudaGetSymbolAddress((void**)&q, g_q);
    float* sc;    cudaGetSymbolAddress((void**)&sc, g_sc);

    rms_kernel<<<TOK, 256>>>(tokens);
    conv_kernel<<<(TOK/4*DIM)/256, 256>>>(tokens, rms_w, conv_w, conv_b);
    // GEMM1: M64 tiles -> grid (1, 32, 8)
    gemm_q<<<dim3(1,32,8), 256>>>(x2, wq, qpart);
    ln_kernel<<<TOK, 128>>>(qln_w);
    // GEMM2: M64 x N128 tiles -> grid (8, 32)
    gemm_sc<<<dim3(8,32,1), 256>>>(q, keys, sc);
    select_kernel<<<TOK, 256>>>(core, out, out_size);
    gather_kernel<<<TOK, 512>>>(mems, out);
}

// round 12
// speedup vs baseline: 1.3095x; 1.1172x over previous
#include <cuda_runtime.h>
#include <cuda_bf16.h>
#include <math.h>

#define BB 2
#define NN 1024
#define TOK (BB*NN)
#define DIM 1024
#define DQK 128
#define NKEY 256
#define TOPK 32
#define DV 512
#define KCONV 5
#define OUT_MAIN (TOK*1024)

__device__ float g_invrms[TOK];
__device__ float g_x2[TOK*DIM];
__device__ float g_qpart[8*TOK*DQK];
__device__ float g_q[TOK*DQK];
__device__ float g_sc[TOK*1024];

__device__ __forceinline__ float fsign(float a, float b){ return (b >= 0.f) ? fabsf(a) : -fabsf(a); }
__device__ __forceinline__ unsigned sortable_f(float f){
    unsigned u = __float_as_uint(f);
    return (u & 0x80000000u) ? ~u : (u | 0x80000000u);
}
__device__ __forceinline__ float unsortable_f(unsigned s){
    unsigned u = (s & 0x80000000u) ? (s ^ 0x80000000u) : ~s;
    return __uint_as_float(u);
}
__device__ __forceinline__ unsigned long long pack_key(float v, unsigned idx){
    return (((unsigned long long)sortable_f(v)) << 32) | (unsigned long long)(0xFFFFFFFFu - idx);
}

// ---------------- LAPACK slasv2 port ----------------
__device__ void slasv2_dev(float f, float g, float h,
                           float& ssmin, float& ssmax,
                           float& snr, float& csr, float& snl, float& csl)
{
    float ft=f, fa=fabsf(f), ht=h, ha=fabsf(h);
    int pmax = 1;
    bool swp = (ha > fa);
    if (swp){ pmax = 3; float t; t=ft; ft=ht; ht=t; t=fa; fa=ha; ha=t; }
    float gt=g, ga=fabsf(g);
    float clt=0.f, crt=0.f, slt=0.f, srt=0.f;
    if (ga == 0.f){
        ssmin = ha; ssmax = fa; clt=1.f; crt=1.f; slt=0.f; srt=0.f;
    } else {
        bool gasmal = true;
        if (ga > fa){
            pmax = 2;
            if ((fa/ga) < 5.9604645e-08f){
                gasmal = false;
                ssmax = ga;
                ssmin = (ha > 1.f) ? (fa/(ga/ha)) : ((fa/ga)*ha);
                clt = 1.f; slt = ht/gt; srt = 1.f; crt = ft/gt;
            }
        }
        if (gasmal){
            float d_ = fa - ha;
            float l  = (d_ == fa) ? 1.f : d_/fa;
            float m  = gt/ft;
            float t  = 2.f - l;
            float mm = m*m, tt = t*t;
            float s  = sqrtf(tt + mm);
            float r_ = (l == 0.f) ? fabsf(m) : sqrtf(l*l + mm);
            float a_ = 0.5f*(s + r_);
            ssmin = ha/a_;
            ssmax = fa*a_;
            if (mm == 0.f){
                t = (l == 0.f) ? (fsign(2.f, ft)*fsign(1.f, gt))
                               : (gt/fsign(d_, ft) + m/t);
            } else {
                t = (m/(s + t) + m/(r_ + l))*(1.f + a_);
            }
            float l2 = sqrtf(t*t + 4.f);
            crt = 2.f/l2;
            srt = t/l2;
            clt = (crt + srt*m)/a_;
            slt = (ht/ft)*srt/a_;
        }
    }
    if (swp){ csl = srt; snl = crt; csr = slt; snr = clt; }
    else    { csl = clt; snl = slt; csr = crt; snr = srt; }
    float ts = 0.f;
    if (pmax == 1) ts = fsign(1.f, csr)*fsign(1.f, csl)*fsign(1.f, f);
    if (pmax == 2) ts = fsign(1.f, snr)*fsign(1.f, csl)*fsign(1.f, g);
    if (pmax == 3) ts = fsign(1.f, snr)*fsign(1.f, snl)*fsign(1.f, h);
    ssmax = fsign(ssmax, ts);
    ssmin = fsign(ssmin, ts*fsign(1.f, f)*fsign(1.f, h));
}

__device__ void svd2x2(const float* core, int hh, float& u0, float& u1,
                       float& t0, float& t1, float& auxp)
{
    float a = core[hh*4+0], b = core[hh*4+1];
    float c = core[hh*4+2], d = core[hh*4+3];
    float q00=1.f,q01=0.f,q10=0.f,q11=1.f;
    float d1, e1, d2;
    if (c != 0.f){
        float nrm  = sqrtf(a*a + c*c);
        float beta = (a >= 0.f) ? -nrm : nrm;
        float tau  = (beta - a)/beta;
        float v    = c/(a - beta);
        float w    = b + v*d;
        e1 = b - tau*w;
        d2 = d - tau*v*w;
        d1 = beta;
        q00 = 1.f - tau; q01 = -tau*v; q10 = -tau*v; q11 = 1.f - tau*v*v;
    } else { d1 = a; e1 = b; d2 = d; }
    float ssmin, ssmax, snr, csr, snl, csl;
    slasv2_dev(d1, e1, d2, ssmin, ssmax, snr, csr, snl, csl);
    float vt0 = csr, vt1 = snr;
    float s1 = ssmax;
    if (s1 < 0.f){ s1 = -s1; vt0 = -vt0; vt1 = -vt1; }
    float s2 = fabsf(ssmin);
    u0 = q00*csl + q01*snl;
    u1 = q10*csl + q11*snl;
    t0 = vt0;
    t1 = vt1;
    float r = s2 - 0.15f;
    auxp = (r > 0.f) ? r*r : 0.f;
}

__global__ void rms_kernel(const float* __restrict__ tokens)
{
    int tok = blockIdx.x;
    const float4* p = (const float4*)(tokens + (size_t)tok*DIM);
    float4 v = p[threadIdx.x];
    float s = v.x*v.x + v.y*v.y + v.z*v.z + v.w*v.w;
    for (int o = 16; o; o >>= 1) s += __shfl_xor_sync(0xFFFFFFFFu, s, o);
    __shared__ float ws[8];
    if ((threadIdx.x & 31) == 0) ws[threadIdx.x >> 5] = s;
    __syncthreads();
    if (threadIdx.x == 0){
        float t = 0.f;
        #pragma unroll
        for (int i = 0; i < 8; i++) t += ws[i];
        g_invrms[tok] = rsqrtf(t*(1.f/1024.f) + 1.1920929e-07f);
    }
}

// conv: thread computes 4 consecutive d (float4) x 4 consecutive n
__global__ void conv_kernel(const float* __restrict__ tokens,
                            const float* __restrict__ rms_w,
                            const float* __restrict__ conv_w,
                            const float* __restrict__ conv_b)
{
    int gid = blockIdx.x*256 + threadIdx.x;     // (TOK/4)*(DIM/4) threads
    int d4  = gid & (DIM/4 - 1);
    int grp = gid >> 8;
    int ng  = grp & (NN/4 - 1);
    int bb  = grp >> 8;
    int d   = d4*4;
    float4 rw = *(const float4*)(rms_w + d);
    float4 cb = *(const float4*)(conv_b + d);
    float wv[4][KCONV];
    #pragma unroll
    for (int dd = 0; dd < 4; dd++)
        #pragma unroll
        for (int k = 0; k < KCONV; k++) wv[dd][k] = conv_w[(d+dd)*KCONV + k];
    float4 xv[8];
    #pragma unroll
    for (int j = 0; j < 8; j++){
        int nn = ng*4 - 4 + j;
        if (nn >= 0){
            int t2 = (bb << 10) + nn;
            float ir = g_invrms[t2];
            float4 x = *(const float4*)(tokens + (size_t)t2*DIM + d);
            xv[j].x = x.x*ir*rw.x; xv[j].y = x.y*ir*rw.y;
            xv[j].z = x.z*ir*rw.z; xv[j].w = x.w*ir*rw.w;
        } else xv[j] = make_float4(0.f,0.f,0.f,0.f);
    }
    #pragma unroll
    for (int i = 0; i < 4; i++){
        float4 acc = cb;
        #pragma unroll
        for (int k = 0; k < KCONV; k++){
            acc.x += wv[0][k]*xv[i+k].x;
            acc.y += wv[1][k]*xv[i+k].y;
            acc.z += wv[2][k]*xv[i+k].z;
            acc.w += wv[3][k]*xv[i+k].w;
        }
        *(float4*)(g_x2 + (size_t)((bb << 10) + ng*4 + i)*DIM + d) = acc;
    }
}

// GEMM1: qpart[z] = x2 @ wq^T, split-K=8.  Tile M64 x N128, 256 thr, 8x4 acc.
__global__ __launch_bounds__(256) void gemm_q(const float* __restrict__ A,
                                              const float* __restrict__ B,
                                              float* __restrict__ C)
{
    __shared__ float As[2][16][68];
    __shared__ float Bs[2][16][132];
    int tid = threadIdx.x, tx = tid & 31, ty = tid >> 5;
    int m0 = blockIdx.y*64, k0 = blockIdx.z*128;
    C += (size_t)blockIdx.z*(TOK*DQK);
    const float* Ab = A + (size_t)m0*DIM + k0;
    const float* Bb = B + k0;
    float acc[8][4];
    #pragma unroll
    for (int i = 0; i < 8; i++)
        #pragma unroll
        for (int j = 0; j < 4; j++) acc[i][j] = 0.f;
    float ra[4], rb[8];
    #pragma unroll
    for (int e = 0; e < 4; e++){ int f = tid + e*256; ra[e] = Ab[(size_t)(f >> 4)*DIM + (f & 15)]; }
    #pragma unroll
    for (int e = 0; e < 8; e++){ int f = tid + e*256; rb[e] = Bb[(size_t)(f >> 4)*DIM + (f & 15)]; }
    #pragma unroll
    for (int e = 0; e < 4; e++){ int f = tid + e*256; As[0][f & 15][f >> 4] = ra[e]; }
    #pragma unroll
    for (int e = 0; e < 8; e++){ int f = tid + e*256; Bs[0][f & 15][f >> 4] = rb[e]; }
    __syncthreads();
    int cur = 0;
    for (int kk = 0; kk < 128; kk += 16){
        bool nxt = (kk + 16) < 128;
        if (nxt){
            #pragma unroll
            for (int e = 0; e < 4; e++){ int f = tid + e*256; ra[e] = Ab[(size_t)(f >> 4)*DIM + kk + 16 + (f & 15)]; }
            #pragma unroll
            for (int e = 0; e < 8; e++){ int f = tid + e*256; rb[e] = Bb[(size_t)(f >> 4)*DIM + kk + 16 + (f & 15)]; }
        }
        #pragma unroll
        for (int k = 0; k < 16; k++){
            float4 a0 = *(const float4*)&As[cur][k][ty*8];
            float4 a1 = *(const float4*)&As[cur][k][ty*8+4];
            float4 b0 = *(const float4*)&Bs[cur][k][tx*4];
            float a[8] = {a0.x,a0.y,a0.z,a0.w,a1.x,a1.y,a1.z,a1.w};
            float b[4] = {b0.x,b0.y,b0.z,b0.w};
            #pragma unroll
            for (int i = 0; i < 8; i++)
                #pragma unroll
                for (int j = 0; j < 4; j++)
                    acc[i][j] += a[i]*b[j];
        }
        if (nxt){
            #pragma unroll
            for (int e = 0; e < 4; e++){ int f = tid + e*256; As[cur^1][f & 15][f >> 4] = ra[e]; }
            #pragma unroll
            for (int e = 0; e < 8; e++){ int f = tid + e*256; Bs[cur^1][f & 15][f >> 4] = rb[e]; }
            __syncthreads();
            cur ^= 1;
        }
    }
    #pragma unroll
    for (int i = 0; i < 8; i++){
        float4 v = {acc[i][0], acc[i][1], acc[i][2], acc[i][3]};
        *(float4*)(C + (size_t)(m0 + ty*8 + i)*DQK + tx*4) = v;
    }
}

// GEMM2: sc = q @ kp^T with fused keys permutation.  Tile M64 x N128, 8x4 acc.
__global__ __launch_bounds__(256) void gemm_sc(const float* __restrict__ A,
                                               const float* __restrict__ keys,
                                               float* __restrict__ C)
{
    __shared__ float As[2][16][68];
    __shared__ float Bs[2][16][132];
    int tid = threadIdx.x, tx = tid & 31, ty = tid >> 5;
    int m0 = blockIdx.y*64, n0 = blockIdx.x*128;
    const float* Ab = A + (size_t)m0*DQK;
    unsigned brow[8];
    #pragma unroll
    for (int e = 0; e < 8; e++){
        int f = tid + e*256;
        int j = n0 + (f >> 4);
        int c = j >> 9, rem = j & 511, m = rem >> 1, r = rem & 1;
        brow[e] = (unsigned)(((c*2 + r)*NKEY + m))*DQK;
    }
    float acc[8][4];
    #pragma unroll
    for (int i = 0; i < 8; i++)
        #pragma unroll
        for (int j = 0; j < 4; j++) acc[i][j] = 0.f;
    float ra[4], rb[8];
    #pragma unroll
    for (int e = 0; e < 4; e++){ int f = tid + e*256; ra[e] = Ab[(size_t)(f >> 4)*DQK + (f & 15)]; }
    #pragma unroll
    for (int e = 0; e < 8; e++){ int f = tid + e*256; rb[e] = keys[brow[e] + (f & 15)]; }
    #pragma unroll
    for (int e = 0; e < 4; e++){ int f = tid + e*256; As[0][f & 15][f >> 4] = ra[e]; }
    #pragma unroll
    for (int e = 0; e < 8; e++){ int f = tid + e*256; Bs[0][f & 15][f >> 4] = rb[e]; }
    __syncthreads();
    int cur = 0;
    for (int kk = 0; kk < 128; kk += 16){
        bool nxt = (kk + 16) < 128;
        if (nxt){
            #pragma unroll
            for (int e = 0; e < 4; e++){ int f = tid + e*256; ra[e] = Ab[(size_t)(f >> 4)*DQK + kk + 16 + (f & 15)]; }
            #pragma unroll
            for (int e = 0; e < 8; e++){ int f = tid + e*256; rb[e] = keys[brow[e] + kk + 16 + (f & 15)]; }
        }
        #pragma unroll
        for (int k = 0; k < 16; k++){
            float4 a0 = *(const float4*)&As[cur][k][ty*8];
            float4 a1 = *(const float4*)&As[cur][k][ty*8+4];
            float4 b0 = *(const float4*)&Bs[cur][k][tx*4];
            float a[8] = {a0.x,a0.y,a0.z,a0.w,a1.x,a1.y,a1.z,a1.w};
            float b[4] = {b0.x,b0.y,b0.z,b0.w};
            #pragma unroll
            for (int i = 0; i < 8; i++)
                #pragma unroll
                for (int j = 0; j < 4; j++)
                    acc[i][j] += a[i]*b[j];
        }
        if (nxt){
            #pragma unroll
            for (int e = 0; e < 4; e++){ int f = tid + e*256; As[cur^1][f & 15][f >> 4] = ra[e]; }
            #pragma unroll
            for (int e = 0; e < 8; e++){ int f = tid + e*256; Bs[cur^1][f & 15][f >> 4] = rb[e]; }
            __syncthreads();
            cur ^= 1;
        }
    }
    #pragma unroll
    for (int i = 0; i < 8; i++){
        float4 v = {acc[i][0], acc[i][1], acc[i][2], acc[i][3]};
        *(float4*)(C + (size_t)(m0 + ty*8 + i)*1024 + n0 + tx*4) = v;
    }
}

// ln: warp-per-token, float4 per lane, shuffle-only reductions
__global__ void ln_kernel(const float* __restrict__ qln_w)
{
    int w = threadIdx.x >> 5, l = threadIdx.x & 31;
    int tok = blockIdx.x*4 + w;
    int col = l*4;
    float4 v = make_float4(0.f,0.f,0.f,0.f);
    #pragma unroll
    for (int z = 0; z < 8; z++){
        float4 p = *(const float4*)(g_qpart + (size_t)z*TOK*DQK + tok*DQK + col);
        v.x += p.x; v.y += p.y; v.z += p.z; v.w += p.w;
    }
    float s = v.x + v.y + v.z + v.w;
    #pragma unroll
    for (int o = 16; o; o >>= 1) s += __shfl_xor_sync(0xFFFFFFFFu, s, o);
    float mu = s * (1.f/128.f);
    float4 dv = {v.x-mu, v.y-mu, v.z-mu, v.w-mu};
    float s2 = dv.x*dv.x + dv.y*dv.y + dv.z*dv.z + dv.w*dv.w;
    #pragma unroll
    for (int o = 16; o; o >>= 1) s2 += __shfl_xor_sync(0xFFFFFFFFu, s2, o);
    float inv = rsqrtf(s2*(1.f/128.f) + 1e-5f);
    float4 qw = *(const float4*)(qln_w + col);
    float4 r = {dv.x*inv*qw.x, dv.y*inv*qw.y, dv.z*inv*qw.z, dv.w*inv*qw.w};
    *(float4*)(g_q + tok*DQK + col) = r;
}

// ---------------- block-wide exact top-32 threshold via MSB radix descent ----------------
__device__ unsigned long long radix_select32(const unsigned long long* kv, int npt, int tid,
                                             unsigned* hist, unsigned* sh)
{
    unsigned long long prefix = 0;
    bool act[4] = {true, true, true, true};
    int need = 32;
    int lane = tid & 31, w = tid >> 5;
    for (int shift = 56; shift >= 0; shift -= 8){
        hist[tid] = 0;
        __syncthreads();
        #pragma unroll
        for (int e = 0; e < 4; e++)
            if (e < npt && act[e])
                atomicAdd(&hist[(unsigned)((kv[e] >> shift) & 255)], 1u);
        __syncthreads();
        unsigned h = hist[tid];
        unsigned inc = h;
        #pragma unroll
        for (int off = 1; off < 32; off <<= 1){
            unsigned v = __shfl_down_sync(0xFFFFFFFFu, inc, off);
            if (lane + off < 32) inc += v;
        }
        if (lane == 0) sh[8 + w] = inc;
        __syncthreads();
        unsigned upper = 0;
        #pragma unroll
        for (int ww = 1; ww < 8; ww++) if (ww > w) upper += sh[8 + ww];
        unsigned cge = inc + upper;
        unsigned cgt = cge - h;
        if (cgt < (unsigned)need && cge >= (unsigned)need){
            sh[0] = (unsigned)tid;
            sh[1] = (unsigned)need - cgt;
            sh[2] = (h == (unsigned)need - cgt) ? 1u : 0u;
        }
        __syncthreads();
        unsigned D = sh[0];
        need = (int)sh[1];
        unsigned done = sh[2];
        prefix |= ((unsigned long long)D) << shift;
        if (done) return prefix;
        #pragma unroll
        for (int e = 0; e < 4; e++)
            if (e < npt)
                act[e] = act[e] && (((kv[e] >> shift) & 255) == (unsigned long long)D);
        __syncthreads();
    }
    return prefix;
}

// ---------------- fused SVD + two-level top-k + memory gather ----------------
__global__ __launch_bounds__(256) void select_gather_kernel(const float* __restrict__ core,
                                                            const float* __restrict__ mem,
                                                            float* __restrict__ d_out, int out_size)
{
    __shared__ float rs[1024];
    __shared__ unsigned hist[256];
    __shared__ unsigned sh[16];
    __shared__ int ridx[32], cidx[32];
    __shared__ float gg0[32], gg1[32], fc0[32], fc1[32];
    __shared__ float suv[8];
    __shared__ int cnt;
    __shared__ float sfs[2][TOPK];
    __shared__ int   sfidx[2][TOPK];
    int tok = blockIdx.x, tid = threadIdx.x;
    if (tid == 0){
        float aux = 0.f;
        #pragma unroll
        for (int hh = 0; hh < 2; hh++){
            float u0,u1,t0,t1,ap;
            svd2x2(core, hh, u0, u1, t0, t1, ap);
            suv[hh*4+0]=u0; suv[hh*4+1]=u1; suv[hh*4+2]=t0; suv[hh*4+3]=t1;
            aux += ap;
        }
        if (tok == 0 && out_size > OUT_MAIN) d_out[OUT_MAIN] = aux*0.1f;
    }
    #pragma unroll
    for (int e = 0; e < 4; e++) rs[tid + e*256] = g_sc[(size_t)tok*1024 + tid + e*256];
    __syncthreads();

    for (int h = 0; h < 2; h++){
        float u0 = suv[h*4+0], u1 = suv[h*4+1];
        float t0 = suv[h*4+2], t1 = suv[h*4+3];
        float c00 = core[h*4+0], c01 = core[h*4+1], c10 = core[h*4+2], c11 = core[h*4+3];

        if (tid == 0) cnt = 0;
        unsigned long long kr = pack_key(rs[2*tid]*u0 + rs[2*tid+1]*u1, (unsigned)tid);
        unsigned long long T = radix_select32(&kr, 1, tid, hist, sh);
        if (kr >= T){ int s = atomicAdd(&cnt, 1); ridx[s] = tid; }
        __syncthreads();
        if (tid < 32){
            int mi = ridx[tid];
            float f0 = rs[2*mi], f1 = rs[2*mi+1];
            gg0[tid] = f0*c00 + f1*c10;
            gg1[tid] = f0*c01 + f1*c11;
        }

        if (tid == 0) cnt = 0;
        unsigned long long kc = pack_key(rs[512 + 2*tid]*t0 + rs[512 + 2*tid+1]*t1, (unsigned)tid);
        T = radix_select32(&kc, 1, tid, hist, sh);
        if (kc >= T){ int s = atomicAdd(&cnt, 1); cidx[s] = tid; }
        __syncthreads();
        if (tid < 32){
            int mi = cidx[tid];
            fc0[tid] = rs[512 + 2*mi];
            fc1[tid] = rs[512 + 2*mi+1];
        }
        __syncthreads();

        if (tid == 0) cnt = 0;
        unsigned long long kv[4];
        #pragma unroll
        for (int c = 0; c < 4; c++){
            int p = c*256 + tid;
            int i = p >> 5, j = p & 31;
            float val = gg0[i]*fc0[j] + gg1[i]*fc1[j];
            kv[c] = pack_key(val, (unsigned)p);
        }
        T = radix_select32(kv, 4, tid, hist, sh);
        #pragma unroll
        for (int c = 0; c < 4; c++){
            if (kv[c] >= T){
                int s = atomicAdd(&cnt, 1);
                int p = (int)(0xFFFFFFFFu - (unsigned)(kv[c] & 0xFFFFFFFFu));
                float val = unsortable_f((unsigned)(kv[c] >> 32));
                sfs[h][s]   = 1.f/(1.f + expf(-val));
                sfidx[h][s] = ridx[p >> 5]*NKEY + cidx[p & 31];
            }
        }
        __syncthreads();
    }

    // gather phase: h = tid>>7, t = tid&127 covers DV/4 float4 columns
    int h = tid >> 7, t = tid & 127;
    float4 acc = {0.f,0.f,0.f,0.f};
    #pragma unroll 8
    for (int k = 0; k < TOPK; k++){
        const float4* row = (const float4*)(mem + (size_t)sfidx[h][k]*DV);
        float4 v = __ldg(row + t);
        float ww = sfs[h][k];
        acc.x += ww*v.x; acc.y += ww*v.y; acc.z += ww*v.z; acc.w += ww*v.w;
    }
    ((float4*)(d_out + (size_t)tok*1024 + h*DV))[t] = acc;
}

extern "C" void kernel_launch(void* const* d_in, const int* in_sizes, int n_in,
                              void* d_out, int out_size)
{
    const float* tokens  = (const float*)d_in[0];
    const float* rms_w   = (const float*)d_in[1];
    const float* conv_w  = (const float*)d_in[2];
    const float* conv_b  = (const float*)d_in[3];
    const float* wq      = (const float*)d_in[4];
    const float* qln_w   = (const float*)d_in[5];
    const float* keys    = (const float*)d_in[6];
    const float* core    = (const float*)d_in[7];
    const float* mems    = (const float*)d_in[8];
    float* out = (float*)d_out;

    float* qpart; cudaGetSymbolAddress((void**)&qpart, g_qpart);
    float* x2;    cudaGetSymbolAddress((void**)&x2, g_x2);
    float* q;     cudaGetSymbolAddress((void**)&q, g_q);
    float* sc;    cudaGetSymbolAddress((void**)&sc, g_sc);

    rms_kernel<<<TOK, 256>>>(tokens);
    conv_kernel<<<(TOK/4)*(DIM/4)/256, 256>>>(tokens, rms_w, conv_w, conv_b);
    gemm_q<<<dim3(1,32,8), 256>>>(x2, wq, qpart);
    ln_kernel<<<TOK/4, 128>>>(qln_w);
    gemm_sc<<<dim3(8,32,1), 256>>>(q, keys, sc);
    select_gather_kernel<<<TOK, 256>>>(core, mems, out, out_size);
}